// round 7
// baseline (speedup 1.0000x reference)
#include <cuda_runtime.h>
#include <cuda_bf16.h>

#define ROW_N 4096
#define THREADS 512
#define RC 0.70710678118654752440f

// Monarch FFT, out = Re(FFT(x)) per 4096-pt row; P = Q = 64, each 64-pt DFT
// split radix-8x8. Real-input Hermitian symmetry halves both stages:
//   B[p,64-k] = conj(B[p,k])          -> stage 1 computes k = 0..32 only
//   Re D[m]   = Re D[4096-m]          -> stage 2 computes k-columns 0..32 only
// Stage-2 thread layout (k 4-distinct per warp, j1 = lane&7) turns all Cs
// column reads into smem broadcasts (1 wavefront per load).

__device__ __forceinline__ float2 cmulf(float2 a, float2 b) {
    return make_float2(fmaf(a.x, b.x, -(a.y * b.y)),
                       fmaf(a.x, b.y,   a.y * b.x));
}

// (bx,by) += h * e^{-2pi i M/8};  sh = r*(hx+hy), dh = r*(hy-hx)
template<int M>
__device__ __forceinline__ void rot_add(float hx, float hy, float sh, float dh,
                                        float& bx, float& by)
{
    if constexpr (M == 0)      { bx += hx; by += hy; }
    else if constexpr (M == 1) { bx += sh; by += dh; }
    else if constexpr (M == 2) { bx += hy; by -= hx; }
    else if constexpr (M == 3) { bx += dh; by -= sh; }
    else if constexpr (M == 4) { bx -= hx; by -= hy; }
    else if constexpr (M == 5) { bx -= sh; by -= dh; }
    else if constexpr (M == 6) { bx -= hy; by += hx; }
    else                       { bx -= dh; by += sh; }
}

template<int M>
__device__ __forceinline__ void rot_add_re(float hx, float hy, float sh, float dh,
                                           float& acc)
{
    if constexpr (M == 0)      acc += hx;
    else if constexpr (M == 1) acc += sh;
    else if constexpr (M == 2) acc += hy;
    else if constexpr (M == 3) acc += dh;
    else if constexpr (M == 4) acc -= hx;
    else if constexpr (M == 5) acc -= sh;
    else if constexpr (M == 6) acc -= hy;
    else                       acc -= dh;
}

template<int K2>
__device__ __forceinline__ void gather8(const float (&Hx)[8], const float (&Hy)[8],
                                        const float (&sH)[8], const float (&dH)[8],
                                        float& bx, float& by)
{
    bx = Hx[0]; by = Hy[0];
    rot_add<(1*K2)&7>(Hx[1],Hy[1],sH[1],dH[1],bx,by);
    rot_add<(2*K2)&7>(Hx[2],Hy[2],sH[2],dH[2],bx,by);
    rot_add<(3*K2)&7>(Hx[3],Hy[3],sH[3],dH[3],bx,by);
    rot_add<(4*K2)&7>(Hx[4],Hy[4],sH[4],dH[4],bx,by);
    rot_add<(5*K2)&7>(Hx[5],Hy[5],sH[5],dH[5],bx,by);
    rot_add<(6*K2)&7>(Hx[6],Hy[6],sH[6],dH[6],bx,by);
    rot_add<(7*K2)&7>(Hx[7],Hy[7],sH[7],dH[7],bx,by);
}

template<int J2>
__device__ __forceinline__ float gather8_re(const float (&Hx)[8], const float (&Hy)[8],
                                            const float (&sH)[8], const float (&dH)[8])
{
    float acc = Hx[0];
    rot_add_re<(1*J2)&7>(Hx[1],Hy[1],sH[1],dH[1],acc);
    rot_add_re<(2*J2)&7>(Hx[2],Hy[2],sH[2],dH[2],acc);
    rot_add_re<(3*J2)&7>(Hx[3],Hy[3],sH[3],dH[3],acc);
    rot_add_re<(4*J2)&7>(Hx[4],Hy[4],sH[4],dH[4],acc);
    rot_add_re<(5*J2)&7>(Hx[5],Hy[5],sH[5],dH[5],acc);
    rot_add_re<(6*J2)&7>(Hx[6],Hy[6],sH[6],dH[6],acc);
    rot_add_re<(7*J2)&7>(Hx[7],Hy[7],sH[7],dH[7],acc);
    return acc;
}

__global__ void __launch_bounds__(THREADS, 2)
monarch_fft_kernel(const float* __restrict__ x, float* __restrict__ out)
{
    __shared__ float2 Cs[64 * 65];   // C[p][k], pitch 65
    __shared__ float2 T64[64];       // e^{-2pi i t/64}
    __shared__ float2 Tf [64];       // e^{-2pi i t/4096}
    float* xs = (float*)Cs;          // overlay; dead before C writes

    const int tid = threadIdx.x;
    const int row = blockIdx.x;

    if (tid < 64) {
        float s, c;
        __sincosf(-6.28318530717958647692f * (float)tid * (1.0f / 64.0f), &s, &c);
        T64[tid] = make_float2(c, s);
        __sincosf(-6.28318530717958647692f * (float)tid * (1.0f / 4096.0f), &s, &c);
        Tf[tid] = make_float2(c, s);
    }

    {   // coalesced 16B row load
        const float4* __restrict__ xr4 = (const float4*)(x + (size_t)row * ROW_N);
        float4* xs4 = (float4*)xs;
        xs4[tid]       = xr4[tid];
        xs4[tid + 512] = xr4[tid + 512];
    }
    __syncthreads();

    // ================= Stage 1: thread = (p, k1), k = k1+8K2 <= 32 ==========
    const int p  = tid & 63;
    const int k1 = tid >> 6;                       // warp-uniform 0..7

    float2 w8q[8];
    #pragma unroll
    for (int m = 1; m < 8; m++) w8q[m] = T64[(8 * m * k1) & 63];

    float Hx[8], Hy[8], sH[8], dH[8];
    #pragma unroll
    for (int q1 = 0; q1 < 8; q1++) {
        float gx = xs[p + 64 * q1];
        float gy = 0.f;
        #pragma unroll
        for (int q2 = 1; q2 < 8; q2++) {
            const float a = xs[p + 64 * q1 + 512 * q2];
            gx = fmaf(a, w8q[q2].x, gx);
            gy = fmaf(a, w8q[q2].y, gy);
        }
        const float2 W = T64[(q1 * k1) & 63];
        Hx[q1] = fmaf(gx, W.x, -(gy * W.y));
        Hy[q1] = fmaf(gx, W.y,   gy * W.x);
    }
    #pragma unroll
    for (int q1 = 0; q1 < 8; q1++) {
        sH[q1] = RC * (Hx[q1] + Hy[q1]);
        dH[q1] = RC * (Hy[q1] - Hx[q1]);
    }

    const float2 T64p = T64[p];
    float2 cur, stp;
    {
        const int t0 = p * k1;
        cur = cmulf(T64[t0 >> 6], Tf[t0 & 63]);    // w4096^{p k1}
        const int ts = 8 * p;
        stp = cmulf(T64[ts >> 6], Tf[ts & 63]);    // w4096^{8p}
    }
    __syncthreads();                               // all xs reads complete

    float2* __restrict__ Crow = Cs + p * 65;
    #define S1_STEP(K2) { \
        float bx, by; gather8<K2>(Hx, Hy, sH, dH, bx, by); \
        Crow[k1 + 8 * K2] = make_float2(fmaf(bx, cur.x, -(by * cur.y)), \
                                        fmaf(bx, cur.y,   by * cur.x)); \
        if (k1 + 8 * K2 > 0) {   /* warp-uniform: only k1==0,K2==0 skips */ \
            const float mx = fmaf(T64p.x, cur.x,   T64p.y * cur.y);  \
            const float my = fmaf(T64p.y, cur.x, -(T64p.x * cur.y)); \
            Crow[64 - (k1 + 8 * K2)] = make_float2(                  \
                fmaf(bx, mx,   by * my),                             \
                fmaf(bx, my, -(by * mx)));                           \
        } \
        cur = cmulf(cur, stp); }
    S1_STEP(0) S1_STEP(1) S1_STEP(2) S1_STEP(3)
    #undef S1_STEP
    if (k1 == 0) {                                 // k = 32 (self-mirrored)
        float bx, by; gather8<4>(Hx, Hy, sH, dH, bx, by);
        Crow[32] = make_float2(fmaf(bx, cur.x, -(by * cur.y)),
                               fmaf(bx, cur.y,   by * cur.x));
    }
    __syncthreads();

    // ========== Stage 2: k = (tid>>3)&31, j1 = tid&7, h = tid>>8 ============
    // h (warp-uniform) selects gather half j2 in {4h..4h+3}.
    const int k  = (tid >> 3) & 31;
    const int j1 = tid & 7;
    const int h  = tid >> 8;

    float2 w8j[8];
    #pragma unroll
    for (int m = 1; m < 8; m++) w8j[m] = T64[(8 * m * j1) & 63];

    float Ix[8], Iy[8], sI[8], dI[8];
    #pragma unroll
    for (int p1 = 0; p1 < 8; p1++) {
        float2 z0 = Cs[p1 * 65 + k];               // 4 distinct addrs -> 1 wf
        float ex = z0.x, ey = z0.y;
        #pragma unroll
        for (int p2 = 1; p2 < 8; p2++) {
            const float2 z = Cs[(p1 + 8 * p2) * 65 + k];
            ex = fmaf(z.x, w8j[p2].x, fmaf(-z.y, w8j[p2].y, ex));
            ey = fmaf(z.x, w8j[p2].y, fmaf( z.y, w8j[p2].x, ey));
        }
        const float2 W = T64[(p1 * j1) & 63];
        Ix[p1] = fmaf(ex, W.x, -(ey * W.y));
        Iy[p1] = fmaf(ex, W.y,   ey * W.x);
        sI[p1] = RC * (Ix[p1] + Iy[p1]);
        dI[p1] = RC * (Iy[p1] - Ix[p1]);
    }

    float* __restrict__ outr = out + (size_t)row * ROW_N;
    #define S2_STEP(J2) { \
        const float v = gather8_re<J2>(Ix, Iy, sI, dI); \
        const int m = (j1 + 8 * (J2)) * 64 + k; \
        outr[m] = v; \
        if (k >= 1) outr[ROW_N - m] = v;   /* columns 33..63 via mirror */ }
    if (h == 0) { S2_STEP(0) S2_STEP(1) S2_STEP(2) S2_STEP(3) }
    else        { S2_STEP(4) S2_STEP(5) S2_STEP(6) S2_STEP(7) }
    #undef S2_STEP

    // ---- Epilogue: column k = 32 (self-mirrored), j = 0..31 ----
    if (tid < 32) {
        const int j = tid;
        float acc = 0.f;
        int t = 0;
        #pragma unroll 8
        for (int pp = 0; pp < 64; pp++) {
            const float2 c = Cs[pp * 65 + 32];     // single addr -> broadcast
            const float2 w = T64[t];
            acc = fmaf(w.x, c.x, fmaf(-w.y, c.y, acc));
            t = (t + j) & 63;
        }
        const int m = j * 64 + 32;                 // 32..2016
        outr[m] = acc;
        outr[ROW_N - m] = acc;                     // 2080..4064
    }
}

extern "C" void kernel_launch(void* const* d_in, const int* in_sizes, int n_in,
                              void* d_out, int out_size)
{
    const float* x = (const float*)d_in[0];
    const int nrows = in_sizes[0] / ROW_N;         // 4096 rows
    if (nrows <= 0) return;
    monarch_fft_kernel<<<nrows, THREADS>>>(x, (float*)d_out);
}

// round 9
// speedup vs baseline: 1.1442x; 1.1442x over previous
#include <cuda_runtime.h>
#include <cuda_bf16.h>

#define ROW_N 4096
#define THREADS 512
#define RC 0.70710678118654752440f

// Monarch FFT, out = Re(FFT(x)) per 4096-pt row; P = Q = 64, radix-8x8 inside
// each 64-pt DFT. Hermitian symmetry (real input):
//   stage 1: B[p,64-k] = conj(B[p,k])  -> gathers only k<=32, mirror C writes
//   stage 2: Re D[m] = Re D[4096-m]    -> compute j = 0..31 only, mirror-store
// Stage-2 threads: k lane-contiguous (coalesced stores), 4 threads/column,
// each producing 8 j-outputs via a shared 4-point fold of the p2 sums.
// Coverage: direct m = 0..2047; mirror 4096-m for all m >= 1 (k=0 threads'
// mirrors fill column-0 of rows 33..63); m = 2048 by a lone spare thread.

__device__ __forceinline__ float2 cmulf(float2 a, float2 b) {
    return make_float2(fmaf(a.x, b.x, -(a.y * b.y)),
                       fmaf(a.x, b.y,   a.y * b.x));
}

// (bx,by) += h * e^{-2pi i M/8}
template<int M>
__device__ __forceinline__ void rot_add(float hx, float hy, float sh, float dh,
                                        float& bx, float& by)
{
    if constexpr (M == 0)      { bx += hx; by += hy; }
    else if constexpr (M == 1) { bx += sh; by += dh; }
    else if constexpr (M == 2) { bx += hy; by -= hx; }
    else if constexpr (M == 3) { bx += dh; by -= sh; }
    else if constexpr (M == 4) { bx -= hx; by -= hy; }
    else if constexpr (M == 5) { bx -= sh; by -= dh; }
    else if constexpr (M == 6) { bx -= hy; by += hx; }
    else                       { bx -= dh; by += sh; }
}

template<int K2>
__device__ __forceinline__ void gather8(const float (&Hx)[8], const float (&Hy)[8],
                                        const float (&sH)[8], const float (&dH)[8],
                                        float& bx, float& by)
{
    bx = Hx[0]; by = Hy[0];
    rot_add<(1*K2)&7>(Hx[1],Hy[1],sH[1],dH[1],bx,by);
    rot_add<(2*K2)&7>(Hx[2],Hy[2],sH[2],dH[2],bx,by);
    rot_add<(3*K2)&7>(Hx[3],Hy[3],sH[3],dH[3],bx,by);
    rot_add<(4*K2)&7>(Hx[4],Hy[4],sH[4],dH[4],bx,by);
    rot_add<(5*K2)&7>(Hx[5],Hy[5],sH[5],dH[5],bx,by);
    rot_add<(6*K2)&7>(Hx[6],Hy[6],sH[6],dH[6],bx,by);
    rot_add<(7*K2)&7>(Hx[7],Hy[7],sH[7],dH[7],bx,by);
}

// c * e^{-2pi i M/8}
template<int M>
__device__ __forceinline__ float2 crot(float2 c)
{
    if constexpr (M == 0)      return c;
    else if constexpr (M == 1) return make_float2( RC*(c.x+c.y),  RC*(c.y-c.x));
    else if constexpr (M == 2) return make_float2( c.y, -c.x);
    else if constexpr (M == 3) return make_float2( RC*(c.y-c.x), -RC*(c.x+c.y));
    else if constexpr (M == 4) return make_float2(-c.x, -c.y);
    else if constexpr (M == 5) return make_float2(-RC*(c.x+c.y),  RC*(c.x-c.y));
    else if constexpr (M == 6) return make_float2(-c.y,  c.x);
    else                       return make_float2( RC*(c.x-c.y),  RC*(c.x+c.y));
}

// Re( F * e^{-2pi i M/8} )
template<int M>
__device__ __forceinline__ float rot_re(float2 F)
{
    if constexpr (M == 0)      return  F.x;
    else if constexpr (M == 1) return  RC*(F.x+F.y);
    else if constexpr (M == 2) return  F.y;
    else if constexpr (M == 3) return  RC*(F.y-F.x);
    else if constexpr (M == 4) return -F.x;
    else if constexpr (M == 5) return -RC*(F.x+F.y);
    else if constexpr (M == 6) return -F.y;
    else                       return  RC*(F.x-F.y);
}

// Stage-2 per-p1 step: loads column k values for p = P1+8*p2, folds to
// E_m = sum_p2 C * w8^{(G2+2m) p2}, multiplies by w64^{P1(G2+2m)}, and
// accumulates Re( F * w8^{P1 J2} ) for J2 = 2H, 2H+1.
template<int P1, int G2, int H>
__device__ __forceinline__ void s2_p1(const float2* __restrict__ Cs,
                                      const float2* __restrict__ T64,
                                      int k, float (&acc)[8])
{
    const float2 u0 = crot<0        >(Cs[(P1 +  0)*65 + k]);
    const float2 u1 = crot<(G2*1)&7>(Cs[(P1 +  8)*65 + k]);
    const float2 u2 = crot<(G2*2)&7>(Cs[(P1 + 16)*65 + k]);
    const float2 u3 = crot<(G2*3)&7>(Cs[(P1 + 24)*65 + k]);
    const float2 u4 = crot<(G2*4)&7>(Cs[(P1 + 32)*65 + k]);
    const float2 u5 = crot<(G2*5)&7>(Cs[(P1 + 40)*65 + k]);
    const float2 u6 = crot<(G2*6)&7>(Cs[(P1 + 48)*65 + k]);
    const float2 u7 = crot<(G2*7)&7>(Cs[(P1 + 56)*65 + k]);

    const float2 s0 = make_float2(u0.x+u4.x, u0.y+u4.y);
    const float2 s1 = make_float2(u1.x+u5.x, u1.y+u5.y);
    const float2 s2 = make_float2(u2.x+u6.x, u2.y+u6.y);
    const float2 s3 = make_float2(u3.x+u7.x, u3.y+u7.y);

    const float2 Pp = make_float2(s0.x+s2.x, s0.y+s2.y);
    const float2 Qq = make_float2(s1.x+s3.x, s1.y+s3.y);
    const float2 Rr = make_float2(s0.x-s2.x, s0.y-s2.y);
    const float2 Ss = make_float2(s1.x-s3.x, s1.y-s3.y);

    const float2 E0 = make_float2(Pp.x+Qq.x, Pp.y+Qq.y);
    const float2 E2 = make_float2(Pp.x-Qq.x, Pp.y-Qq.y);
    const float2 E1 = make_float2(Rr.x+Ss.y, Rr.y-Ss.x);   // R - i S
    const float2 E3 = make_float2(Rr.x-Ss.y, Rr.y+Ss.x);   // R + i S

    constexpr int JA = 2*H, JB = 2*H + 1;
    {   const float2 F = cmulf(E0, T64[(P1*(G2+0))&63]);
        acc[0] += rot_re<(P1*JA)&7>(F);  acc[1] += rot_re<(P1*JB)&7>(F); }
    {   const float2 F = cmulf(E1, T64[(P1*(G2+2))&63]);
        acc[2] += rot_re<(P1*JA)&7>(F);  acc[3] += rot_re<(P1*JB)&7>(F); }
    {   const float2 F = cmulf(E2, T64[(P1*(G2+4))&63]);
        acc[4] += rot_re<(P1*JA)&7>(F);  acc[5] += rot_re<(P1*JB)&7>(F); }
    {   const float2 F = cmulf(E3, T64[(P1*(G2+6))&63]);
        acc[6] += rot_re<(P1*JA)&7>(F);  acc[7] += rot_re<(P1*JB)&7>(F); }
}

template<int G2, int H>
__device__ __forceinline__ void stage2_run(const float2* __restrict__ Cs,
                                           const float2* __restrict__ T64,
                                           int k, float* __restrict__ outr)
{
    float acc[8];
    #pragma unroll
    for (int i = 0; i < 8; i++) acc[i] = 0.f;
    s2_p1<0,G2,H>(Cs, T64, k, acc);
    s2_p1<1,G2,H>(Cs, T64, k, acc);
    s2_p1<2,G2,H>(Cs, T64, k, acc);
    s2_p1<3,G2,H>(Cs, T64, k, acc);
    s2_p1<4,G2,H>(Cs, T64, k, acc);
    s2_p1<5,G2,H>(Cs, T64, k, acc);
    s2_p1<6,G2,H>(Cs, T64, k, acc);
    s2_p1<7,G2,H>(Cs, T64, k, acc);

    #pragma unroll
    for (int m = 0; m < 4; m++) {
        #pragma unroll
        for (int e = 0; e < 2; e++) {
            const int j  = G2 + 2*m + 8*(2*H + e);     // 0..31
            const int mj = j * 64 + k;                 // 0..2047
            const float v = acc[2*m + e];
            outr[mj] = v;                              // coalesced
            if (mj >= 1) outr[ROW_N - mj] = v;         // covers 2049..4095 AND
        }                                              // col-0 rows 33..63
    }
}

__global__ void __launch_bounds__(THREADS, 2)
monarch_fft_kernel(const float* __restrict__ x, float* __restrict__ out)
{
    __shared__ float2 Cs[64 * 65];   // C[p][k], pitch 65
    __shared__ float2 T64[64];       // e^{-2pi i t/64}
    __shared__ float2 Tf [64];       // e^{-2pi i t/4096}
    float* xs = (float*)Cs;          // overlay; dead before C writes

    const int tid = threadIdx.x;
    const int row = blockIdx.x;

    if (tid < 64) {
        float s, c;
        __sincosf(-6.28318530717958647692f * (float)tid * (1.0f / 64.0f), &s, &c);
        T64[tid] = make_float2(c, s);
        __sincosf(-6.28318530717958647692f * (float)tid * (1.0f / 4096.0f), &s, &c);
        Tf[tid] = make_float2(c, s);
    }

    {   // coalesced 16B row load
        const float4* __restrict__ xr4 = (const float4*)(x + (size_t)row * ROW_N);
        float4* xs4 = (float4*)xs;
        xs4[tid]       = xr4[tid];
        xs4[tid + 512] = xr4[tid + 512];
    }
    __syncthreads();

    // ================= Stage 1: thread = (p, k1), k = k1+8K2 <= 32 ==========
    const int p  = tid & 63;
    const int k1 = tid >> 6;                       // warp-uniform 0..7

    float2 w8q[8];
    #pragma unroll
    for (int m = 1; m < 8; m++) w8q[m] = T64[(8 * m * k1) & 63];

    float Hx[8], Hy[8], sH[8], dH[8];
    #pragma unroll
    for (int q1 = 0; q1 < 8; q1++) {
        float gx = xs[p + 64 * q1];
        float gy = 0.f;
        #pragma unroll
        for (int q2 = 1; q2 < 8; q2++) {
            const float a = xs[p + 64 * q1 + 512 * q2];
            gx = fmaf(a, w8q[q2].x, gx);
            gy = fmaf(a, w8q[q2].y, gy);
        }
        const float2 W = T64[(q1 * k1) & 63];
        Hx[q1] = fmaf(gx, W.x, -(gy * W.y));
        Hy[q1] = fmaf(gx, W.y,   gy * W.x);
    }
    #pragma unroll
    for (int q1 = 0; q1 < 8; q1++) {
        sH[q1] = RC * (Hx[q1] + Hy[q1]);
        dH[q1] = RC * (Hy[q1] - Hx[q1]);
    }

    const float2 T64p = T64[p];
    float2 cur, stp;
    {
        const int t0 = p * k1;
        cur = cmulf(T64[t0 >> 6], Tf[t0 & 63]);    // w4096^{p k1}
        const int ts = 8 * p;
        stp = cmulf(T64[ts >> 6], Tf[ts & 63]);    // w4096^{8p}
    }
    __syncthreads();                               // all xs reads complete

    float2* __restrict__ Crow = Cs + p * 65;
    #define S1_STEP(K2) { \
        float bx, by; gather8<K2>(Hx, Hy, sH, dH, bx, by); \
        Crow[k1 + 8 * K2] = make_float2(fmaf(bx, cur.x, -(by * cur.y)), \
                                        fmaf(bx, cur.y,   by * cur.x)); \
        if (k1 + 8 * K2 > 0) {   /* warp-uniform: only k1==0,K2==0 skips */ \
            const float mx = fmaf(T64p.x, cur.x,   T64p.y * cur.y);  \
            const float my = fmaf(T64p.y, cur.x, -(T64p.x * cur.y)); \
            Crow[64 - (k1 + 8 * K2)] = make_float2(                  \
                fmaf(bx, mx,   by * my),                             \
                fmaf(bx, my, -(by * mx)));                           \
        } \
        cur = cmulf(cur, stp); }
    S1_STEP(0) S1_STEP(1) S1_STEP(2) S1_STEP(3)
    #undef S1_STEP
    if (k1 == 0) {                                 // k = 32 (self-mirrored)
        float bx, by; gather8<4>(Hx, Hy, sH, dH, bx, by);
        Crow[32] = make_float2(fmaf(bx, cur.x, -(by * cur.y)),
                               fmaf(bx, cur.y,   by * cur.x));
    }
    __syncthreads();

    // ===== Stage 2: threads 0..255: k = tid&63 (lane-contiguous), ==========
    // gh = tid>>6 -> (g2 = gh&1, h = gh>>1): j = g2+2m+8(2h+e), j = 0..31.
    float* __restrict__ outr = out + (size_t)row * ROW_N;
    if (tid < 256) {
        const int k  = tid & 63;
        const int gh = tid >> 6;
        if      (gh == 0) stage2_run<0,0>(Cs, T64, k, outr);
        else if (gh == 1) stage2_run<1,0>(Cs, T64, k, outr);
        else if (gh == 2) stage2_run<0,1>(Cs, T64, k, outr);
        else              stage2_run<1,1>(Cs, T64, k, outr);
    } else if (tid == 256) {
        // lone uncovered element m = 2048:  Re D = sum_p (-1)^p Re C[p,0]
        float acc = 0.f;
        #pragma unroll 8
        for (int pp = 0; pp < 64; pp += 2)
            acc += Cs[pp * 65].x - Cs[(pp + 1) * 65].x;
        outr[2048] = acc;
    }
}

extern "C" void kernel_launch(void* const* d_in, const int* in_sizes, int n_in,
                              void* d_out, int out_size)
{
    const float* x = (const float*)d_in[0];
    const int nrows = in_sizes[0] / ROW_N;         // 4096 rows
    if (nrows <= 0) return;
    monarch_fft_kernel<<<nrows, THREADS>>>(x, (float*)d_out);
}

// round 10
// speedup vs baseline: 1.3352x; 1.1669x over previous
#include <cuda_runtime.h>
#include <cuda_bf16.h>

#define ROW_N 4096
#define THREADS 512
#define RC 0.70710678118654752440f

// Monarch FFT, out = Re(FFT(x)) per 4096-pt row; P = Q = 64, radix-8x8 inside
// each 64-pt DFT. Hermitian symmetry (real input) halves both stages.
// Stage 2: 8 threads per k-column. (g2,h) picks 8 j-outputs; the p1-range is
// split across the two CTA halves (p1 0..3 vs 4..7) and partials combined in
// shared memory, so all 512 threads stay busy.

__device__ __forceinline__ float2 cmulf(float2 a, float2 b) {
    return make_float2(fmaf(a.x, b.x, -(a.y * b.y)),
                       fmaf(a.x, b.y,   a.y * b.x));
}

// (bx,by) += h * e^{-2pi i M/8}
template<int M>
__device__ __forceinline__ void rot_add(float hx, float hy, float sh, float dh,
                                        float& bx, float& by)
{
    if constexpr (M == 0)      { bx += hx; by += hy; }
    else if constexpr (M == 1) { bx += sh; by += dh; }
    else if constexpr (M == 2) { bx += hy; by -= hx; }
    else if constexpr (M == 3) { bx += dh; by -= sh; }
    else if constexpr (M == 4) { bx -= hx; by -= hy; }
    else if constexpr (M == 5) { bx -= sh; by -= dh; }
    else if constexpr (M == 6) { bx -= hy; by += hx; }
    else                       { bx -= dh; by += sh; }
}

template<int K2>
__device__ __forceinline__ void gather8(const float (&Hx)[8], const float (&Hy)[8],
                                        const float (&sH)[8], const float (&dH)[8],
                                        float& bx, float& by)
{
    bx = Hx[0]; by = Hy[0];
    rot_add<(1*K2)&7>(Hx[1],Hy[1],sH[1],dH[1],bx,by);
    rot_add<(2*K2)&7>(Hx[2],Hy[2],sH[2],dH[2],bx,by);
    rot_add<(3*K2)&7>(Hx[3],Hy[3],sH[3],dH[3],bx,by);
    rot_add<(4*K2)&7>(Hx[4],Hy[4],sH[4],dH[4],bx,by);
    rot_add<(5*K2)&7>(Hx[5],Hy[5],sH[5],dH[5],bx,by);
    rot_add<(6*K2)&7>(Hx[6],Hy[6],sH[6],dH[6],bx,by);
    rot_add<(7*K2)&7>(Hx[7],Hy[7],sH[7],dH[7],bx,by);
}

// c * e^{-2pi i M/8}
template<int M>
__device__ __forceinline__ float2 crot(float2 c)
{
    if constexpr (M == 0)      return c;
    else if constexpr (M == 1) return make_float2( RC*(c.x+c.y),  RC*(c.y-c.x));
    else if constexpr (M == 2) return make_float2( c.y, -c.x);
    else if constexpr (M == 3) return make_float2( RC*(c.y-c.x), -RC*(c.x+c.y));
    else if constexpr (M == 4) return make_float2(-c.x, -c.y);
    else if constexpr (M == 5) return make_float2(-RC*(c.x+c.y),  RC*(c.x-c.y));
    else if constexpr (M == 6) return make_float2(-c.y,  c.x);
    else                       return make_float2( RC*(c.x-c.y),  RC*(c.x+c.y));
}

// Re( F * e^{-2pi i M/8} )
template<int M>
__device__ __forceinline__ float rot_re(float2 F)
{
    if constexpr (M == 0)      return  F.x;
    else if constexpr (M == 1) return  RC*(F.x+F.y);
    else if constexpr (M == 2) return  F.y;
    else if constexpr (M == 3) return  RC*(F.y-F.x);
    else if constexpr (M == 4) return -F.x;
    else if constexpr (M == 5) return -RC*(F.x+F.y);
    else if constexpr (M == 6) return -F.y;
    else                       return  RC*(F.x-F.y);
}

// One p1 value: load 8 column entries, fold to E_m (4 even-or-odd j1 values),
// rotate by w64^{P1 j1}, accumulate Re parts for J2 = 2H, 2H+1.
template<int P1, int G2, int H>
__device__ __forceinline__ void s2_p1(const float2* __restrict__ Cs,
                                      const float2* __restrict__ T64,
                                      int k, float (&acc)[8])
{
    const float2 u0 = crot<0        >(Cs[(P1 +  0)*65 + k]);
    const float2 u1 = crot<(G2*1)&7>(Cs[(P1 +  8)*65 + k]);
    const float2 u2 = crot<(G2*2)&7>(Cs[(P1 + 16)*65 + k]);
    const float2 u3 = crot<(G2*3)&7>(Cs[(P1 + 24)*65 + k]);
    const float2 u4 = crot<(G2*4)&7>(Cs[(P1 + 32)*65 + k]);
    const float2 u5 = crot<(G2*5)&7>(Cs[(P1 + 40)*65 + k]);
    const float2 u6 = crot<(G2*6)&7>(Cs[(P1 + 48)*65 + k]);
    const float2 u7 = crot<(G2*7)&7>(Cs[(P1 + 56)*65 + k]);

    const float2 s0 = make_float2(u0.x+u4.x, u0.y+u4.y);
    const float2 s1 = make_float2(u1.x+u5.x, u1.y+u5.y);
    const float2 s2 = make_float2(u2.x+u6.x, u2.y+u6.y);
    const float2 s3 = make_float2(u3.x+u7.x, u3.y+u7.y);

    const float2 Pp = make_float2(s0.x+s2.x, s0.y+s2.y);
    const float2 Qq = make_float2(s1.x+s3.x, s1.y+s3.y);
    const float2 Rr = make_float2(s0.x-s2.x, s0.y-s2.y);
    const float2 Ss = make_float2(s1.x-s3.x, s1.y-s3.y);

    const float2 E0 = make_float2(Pp.x+Qq.x, Pp.y+Qq.y);
    const float2 E2 = make_float2(Pp.x-Qq.x, Pp.y-Qq.y);
    const float2 E1 = make_float2(Rr.x+Ss.y, Rr.y-Ss.x);   // R - i S
    const float2 E3 = make_float2(Rr.x-Ss.y, Rr.y+Ss.x);   // R + i S

    constexpr int JA = 2*H, JB = 2*H + 1;
    {   const float2 F = cmulf(E0, T64[(P1*(G2+0))&63]);
        acc[0] += rot_re<(P1*JA)&7>(F);  acc[1] += rot_re<(P1*JB)&7>(F); }
    {   const float2 F = cmulf(E1, T64[(P1*(G2+2))&63]);
        acc[2] += rot_re<(P1*JA)&7>(F);  acc[3] += rot_re<(P1*JB)&7>(F); }
    {   const float2 F = cmulf(E2, T64[(P1*(G2+4))&63]);
        acc[4] += rot_re<(P1*JA)&7>(F);  acc[5] += rot_re<(P1*JB)&7>(F); }
    {   const float2 F = cmulf(E3, T64[(P1*(G2+6))&63]);
        acc[6] += rot_re<(P1*JA)&7>(F);  acc[7] += rot_re<(P1*JB)&7>(F); }
}

// Half of the p1 range (4 values starting at B).
template<int G2, int H, int B>
__device__ __forceinline__ void stage2_half(const float2* __restrict__ Cs,
                                            const float2* __restrict__ T64,
                                            int k, float (&acc)[8])
{
    s2_p1<B+0,G2,H>(Cs, T64, k, acc);
    s2_p1<B+1,G2,H>(Cs, T64, k, acc);
    s2_p1<B+2,G2,H>(Cs, T64, k, acc);
    s2_p1<B+3,G2,H>(Cs, T64, k, acc);
}

__global__ void __launch_bounds__(THREADS, 2)
monarch_fft_kernel(const float* __restrict__ x, float* __restrict__ out)
{
    __shared__ float2 Cs[64 * 65];   // C[p][k], pitch 65   (33.3 KB)
    __shared__ float2 T64[64];       // e^{-2pi i t/64}
    __shared__ float2 Tf [64];       // e^{-2pi i t/4096}
    __shared__ float  Ps[8][256];    // stage-2 partial sums (8 KB)
    float* xs = (float*)Cs;          // overlay; dead before C writes

    const int tid = threadIdx.x;
    const int row = blockIdx.x;

    if (tid < 64) {
        float s, c;
        __sincosf(-6.28318530717958647692f * (float)tid * (1.0f / 64.0f), &s, &c);
        T64[tid] = make_float2(c, s);
        __sincosf(-6.28318530717958647692f * (float)tid * (1.0f / 4096.0f), &s, &c);
        Tf[tid] = make_float2(c, s);
    }

    {   // coalesced 16B row load
        const float4* __restrict__ xr4 = (const float4*)(x + (size_t)row * ROW_N);
        float4* xs4 = (float4*)xs;
        xs4[tid]       = xr4[tid];
        xs4[tid + 512] = xr4[tid + 512];
    }
    __syncthreads();

    // ================= Stage 1: thread = (p, k1), k = k1+8K2 <= 32 ==========
    const int p  = tid & 63;
    const int k1 = tid >> 6;                       // warp-uniform 0..7

    float2 w8q[8];
    #pragma unroll
    for (int m = 1; m < 8; m++) w8q[m] = T64[(8 * m * k1) & 63];

    float Hx[8], Hy[8], sH[8], dH[8];
    #pragma unroll
    for (int q1 = 0; q1 < 8; q1++) {
        float gx = xs[p + 64 * q1];
        float gy = 0.f;
        #pragma unroll
        for (int q2 = 1; q2 < 8; q2++) {
            const float a = xs[p + 64 * q1 + 512 * q2];
            gx = fmaf(a, w8q[q2].x, gx);
            gy = fmaf(a, w8q[q2].y, gy);
        }
        const float2 W = T64[(q1 * k1) & 63];
        Hx[q1] = fmaf(gx, W.x, -(gy * W.y));
        Hy[q1] = fmaf(gx, W.y,   gy * W.x);
    }
    #pragma unroll
    for (int q1 = 0; q1 < 8; q1++) {
        sH[q1] = RC * (Hx[q1] + Hy[q1]);
        dH[q1] = RC * (Hy[q1] - Hx[q1]);
    }

    const float2 T64p = T64[p];
    float2 cur, stp;
    {
        const int t0 = p * k1;
        cur = cmulf(T64[t0 >> 6], Tf[t0 & 63]);    // w4096^{p k1}
        const int ts = 8 * p;
        stp = cmulf(T64[ts >> 6], Tf[ts & 63]);    // w4096^{8p}
    }
    __syncthreads();                               // all xs reads complete

    float2* __restrict__ Crow = Cs + p * 65;
    #define S1_STEP(K2) { \
        float bx, by; gather8<K2>(Hx, Hy, sH, dH, bx, by); \
        Crow[k1 + 8 * K2] = make_float2(fmaf(bx, cur.x, -(by * cur.y)), \
                                        fmaf(bx, cur.y,   by * cur.x)); \
        if (k1 + 8 * K2 > 0) {   /* warp-uniform: only k1==0,K2==0 skips */ \
            const float mx = fmaf(T64p.x, cur.x,   T64p.y * cur.y);  \
            const float my = fmaf(T64p.y, cur.x, -(T64p.x * cur.y)); \
            Crow[64 - (k1 + 8 * K2)] = make_float2(                  \
                fmaf(bx, mx,   by * my),                             \
                fmaf(bx, my, -(by * mx)));                           \
        } \
        cur = cmulf(cur, stp); }
    S1_STEP(0) S1_STEP(1) S1_STEP(2) S1_STEP(3)
    #undef S1_STEP
    if (k1 == 0) {                                 // k = 32 (self-mirrored)
        float bx, by; gather8<4>(Hx, Hy, sH, dH, bx, by);
        Crow[32] = make_float2(fmaf(bx, cur.x, -(by * cur.y)),
                               fmaf(bx, cur.y,   by * cur.x));
    }
    __syncthreads();

    // ===== Stage 2: 8 threads/column. k = tid&63, gh = (tid>>6)&3, =========
    // half = tid>>8 selects p1 range 0..3 / 4..7. j = g2+2m+8(2h+e), 0..31.
    const int k    = tid & 63;
    const int gh   = (tid >> 6) & 3;
    const int half = tid >> 8;

    float acc[8];
    #pragma unroll
    for (int i = 0; i < 8; i++) acc[i] = 0.f;

    if (half == 0) {
        if      (gh == 0) stage2_half<0,0,0>(Cs, T64, k, acc);
        else if (gh == 1) stage2_half<1,0,0>(Cs, T64, k, acc);
        else if (gh == 2) stage2_half<0,1,0>(Cs, T64, k, acc);
        else              stage2_half<1,1,0>(Cs, T64, k, acc);
    } else {
        if      (gh == 0) stage2_half<0,0,4>(Cs, T64, k, acc);
        else if (gh == 1) stage2_half<1,0,4>(Cs, T64, k, acc);
        else if (gh == 2) stage2_half<0,1,4>(Cs, T64, k, acc);
        else              stage2_half<1,1,4>(Cs, T64, k, acc);
        const int u = tid - 256;
        #pragma unroll
        for (int i = 0; i < 8; i++) Ps[i][u] = acc[i];   // conflict-free
    }
    __syncthreads();

    float* __restrict__ outr = out + (size_t)row * ROW_N;
    if (half == 0) {
        const int g2 = gh & 1, h = gh >> 1;
        #pragma unroll
        for (int i = 0; i < 8; i++) acc[i] += Ps[i][tid];
        #pragma unroll
        for (int m = 0; m < 4; m++) {
            #pragma unroll
            for (int e = 0; e < 2; e++) {
                const int j  = g2 + 2*m + 8*(2*h + e);   // 0..31
                const int mj = j * 64 + k;               // 0..2047
                const float v = acc[2*m + e];
                outr[mj] = v;                            // coalesced
                if (mj >= 1) outr[ROW_N - mj] = v;       // mirror (incl col 0)
            }
        }
    } else if (tid == 256) {
        // lone element m = 2048:  Re D = sum_p (-1)^p Re C[p,0]
        float a2 = 0.f;
        #pragma unroll 8
        for (int pp = 0; pp < 64; pp += 2)
            a2 += Cs[pp * 65].x - Cs[(pp + 1) * 65].x;
        outr[2048] = a2;
    }
}

extern "C" void kernel_launch(void* const* d_in, const int* in_sizes, int n_in,
                              void* d_out, int out_size)
{
    const float* x = (const float*)d_in[0];
    const int nrows = in_sizes[0] / ROW_N;         // 4096 rows
    if (nrows <= 0) return;
    monarch_fft_kernel<<<nrows, THREADS>>>(x, (float*)d_out);
}

// round 11
// speedup vs baseline: 1.5363x; 1.1507x over previous
#include <cuda_runtime.h>
#include <cuda_bf16.h>

#define ROW_N 4096
#define THREADS 512
#define RC 0.70710678118654752440f

// Monarch FFT, out = Re(FFT(x)) per 4096-pt row; P = Q = 64, radix-8x8 inside
// each 64-pt DFT. Hermitian symmetry (real input) halves both stages.
// Stage 2: 8 classes = (parity G2) x (quarter Qt); thread handles p1 in
// {Qt, Qt+4}, produces 16 outputs (4 j1 x 4 j2) per fold -> loads deduped 2x.
// Partials exchanged through an overlay on Cs (reads complete first).

__device__ __forceinline__ float2 cmulf(float2 a, float2 b) {
    return make_float2(fmaf(a.x, b.x, -(a.y * b.y)),
                       fmaf(a.x, b.y,   a.y * b.x));
}

// (bx,by) += h * e^{-2pi i M/8}
template<int M>
__device__ __forceinline__ void rot_add(float hx, float hy, float sh, float dh,
                                        float& bx, float& by)
{
    if constexpr (M == 0)      { bx += hx; by += hy; }
    else if constexpr (M == 1) { bx += sh; by += dh; }
    else if constexpr (M == 2) { bx += hy; by -= hx; }
    else if constexpr (M == 3) { bx += dh; by -= sh; }
    else if constexpr (M == 4) { bx -= hx; by -= hy; }
    else if constexpr (M == 5) { bx -= sh; by -= dh; }
    else if constexpr (M == 6) { bx -= hy; by += hx; }
    else                       { bx -= dh; by += sh; }
}

template<int K2>
__device__ __forceinline__ void gather8(const float (&Hx)[8], const float (&Hy)[8],
                                        const float (&sH)[8], const float (&dH)[8],
                                        float& bx, float& by)
{
    bx = Hx[0]; by = Hy[0];
    rot_add<(1*K2)&7>(Hx[1],Hy[1],sH[1],dH[1],bx,by);
    rot_add<(2*K2)&7>(Hx[2],Hy[2],sH[2],dH[2],bx,by);
    rot_add<(3*K2)&7>(Hx[3],Hy[3],sH[3],dH[3],bx,by);
    rot_add<(4*K2)&7>(Hx[4],Hy[4],sH[4],dH[4],bx,by);
    rot_add<(5*K2)&7>(Hx[5],Hy[5],sH[5],dH[5],bx,by);
    rot_add<(6*K2)&7>(Hx[6],Hy[6],sH[6],dH[6],bx,by);
    rot_add<(7*K2)&7>(Hx[7],Hy[7],sH[7],dH[7],bx,by);
}

// c * e^{-2pi i M/8}
template<int M>
__device__ __forceinline__ float2 crot(float2 c)
{
    if constexpr (M == 0)      return c;
    else if constexpr (M == 1) return make_float2( RC*(c.x+c.y),  RC*(c.y-c.x));
    else if constexpr (M == 2) return make_float2( c.y, -c.x);
    else if constexpr (M == 3) return make_float2( RC*(c.y-c.x), -RC*(c.x+c.y));
    else if constexpr (M == 4) return make_float2(-c.x, -c.y);
    else if constexpr (M == 5) return make_float2(-RC*(c.x+c.y),  RC*(c.x-c.y));
    else if constexpr (M == 6) return make_float2(-c.y,  c.x);
    else                       return make_float2( RC*(c.x-c.y),  RC*(c.x+c.y));
}

// Re( F * e^{-2pi i M/8} )
template<int M>
__device__ __forceinline__ float rot_re(float2 F)
{
    if constexpr (M == 0)      return  F.x;
    else if constexpr (M == 1) return  RC*(F.x+F.y);
    else if constexpr (M == 2) return  F.y;
    else if constexpr (M == 3) return  RC*(F.y-F.x);
    else if constexpr (M == 4) return -F.x;
    else if constexpr (M == 5) return -RC*(F.x+F.y);
    else if constexpr (M == 6) return -F.y;
    else                       return  RC*(F.x-F.y);
}

// One p1: 8 loads -> E_m for j1 = G2+2m -> F_m -> accumulate Re for j2 = 0..3.
// acc[m*4+j2] corresponds to output j = (G2+2m) + 8*j2.
template<int P1, int G2>
__device__ __forceinline__ void s2_p1(const float2* __restrict__ Cs,
                                      const float2* __restrict__ T64,
                                      int k, float (&acc)[16])
{
    const float2 u0 = crot<0        >(Cs[(P1 +  0)*65 + k]);
    const float2 u1 = crot<(G2*1)&7>(Cs[(P1 +  8)*65 + k]);
    const float2 u2 = crot<(G2*2)&7>(Cs[(P1 + 16)*65 + k]);
    const float2 u3 = crot<(G2*3)&7>(Cs[(P1 + 24)*65 + k]);
    const float2 u4 = crot<(G2*4)&7>(Cs[(P1 + 32)*65 + k]);
    const float2 u5 = crot<(G2*5)&7>(Cs[(P1 + 40)*65 + k]);
    const float2 u6 = crot<(G2*6)&7>(Cs[(P1 + 48)*65 + k]);
    const float2 u7 = crot<(G2*7)&7>(Cs[(P1 + 56)*65 + k]);

    const float2 s0 = make_float2(u0.x+u4.x, u0.y+u4.y);
    const float2 s1 = make_float2(u1.x+u5.x, u1.y+u5.y);
    const float2 s2 = make_float2(u2.x+u6.x, u2.y+u6.y);
    const float2 s3 = make_float2(u3.x+u7.x, u3.y+u7.y);

    const float2 Pp = make_float2(s0.x+s2.x, s0.y+s2.y);
    const float2 Qq = make_float2(s1.x+s3.x, s1.y+s3.y);
    const float2 Rr = make_float2(s0.x-s2.x, s0.y-s2.y);
    const float2 Ss = make_float2(s1.x-s3.x, s1.y-s3.y);

    const float2 E0 = make_float2(Pp.x+Qq.x, Pp.y+Qq.y);
    const float2 E2 = make_float2(Pp.x-Qq.x, Pp.y-Qq.y);
    const float2 E1 = make_float2(Rr.x+Ss.y, Rr.y-Ss.x);   // R - i S
    const float2 E3 = make_float2(Rr.x-Ss.y, Rr.y+Ss.x);   // R + i S

    {   const float2 F = cmulf(E0, T64[(P1*(G2+0))&63]);
        acc[ 0] += rot_re<0        >(F);
        acc[ 1] += rot_re<(P1*1)&7>(F);
        acc[ 2] += rot_re<(P1*2)&7>(F);
        acc[ 3] += rot_re<(P1*3)&7>(F); }
    {   const float2 F = cmulf(E1, T64[(P1*(G2+2))&63]);
        acc[ 4] += rot_re<0        >(F);
        acc[ 5] += rot_re<(P1*1)&7>(F);
        acc[ 6] += rot_re<(P1*2)&7>(F);
        acc[ 7] += rot_re<(P1*3)&7>(F); }
    {   const float2 F = cmulf(E2, T64[(P1*(G2+4))&63]);
        acc[ 8] += rot_re<0        >(F);
        acc[ 9] += rot_re<(P1*1)&7>(F);
        acc[10] += rot_re<(P1*2)&7>(F);
        acc[11] += rot_re<(P1*3)&7>(F); }
    {   const float2 F = cmulf(E3, T64[(P1*(G2+6))&63]);
        acc[12] += rot_re<0        >(F);
        acc[13] += rot_re<(P1*1)&7>(F);
        acc[14] += rot_re<(P1*2)&7>(F);
        acc[15] += rot_re<(P1*3)&7>(F); }
}

template<int G2, int Qt>
__device__ __forceinline__ void stage2_quarter(const float2* __restrict__ Cs,
                                               const float2* __restrict__ T64,
                                               int k, float (&acc)[16])
{
    s2_p1<Qt,     G2>(Cs, T64, k, acc);
    s2_p1<Qt + 4, G2>(Cs, T64, k, acc);
}

__global__ void __launch_bounds__(THREADS, 2)
monarch_fft_kernel(const float* __restrict__ x, float* __restrict__ out)
{
    __shared__ float2 Cs[64 * 65];   // C[p][k], pitch 65  (33.3 KB)
    __shared__ float2 T64[64];       // e^{-2pi i t/64}
    __shared__ float2 Tf [64];       // e^{-2pi i t/4096}
    float* xs  = (float*)Cs;         // stage-1 input overlay
    float* Pov = (float*)Cs;         // stage-2 partial overlay (after reads)

    const int tid = threadIdx.x;
    const int row = blockIdx.x;

    if (tid < 64) {
        float s, c;
        __sincosf(-6.28318530717958647692f * (float)tid * (1.0f / 64.0f), &s, &c);
        T64[tid] = make_float2(c, s);
        __sincosf(-6.28318530717958647692f * (float)tid * (1.0f / 4096.0f), &s, &c);
        Tf[tid] = make_float2(c, s);
    }

    {   // coalesced 16B row load
        const float4* __restrict__ xr4 = (const float4*)(x + (size_t)row * ROW_N);
        float4* xs4 = (float4*)xs;
        xs4[tid]       = xr4[tid];
        xs4[tid + 512] = xr4[tid + 512];
    }
    __syncthreads();

    // ================= Stage 1: thread = (p, k1), k = k1+8K2 <= 32 ==========
    const int p  = tid & 63;
    const int k1 = tid >> 6;                       // warp-uniform 0..7

    float2 w8q[8];
    #pragma unroll
    for (int m = 1; m < 8; m++) w8q[m] = T64[(8 * m * k1) & 63];

    float Hx[8], Hy[8], sH[8], dH[8];
    #pragma unroll
    for (int q1 = 0; q1 < 8; q1++) {
        float gx = xs[p + 64 * q1];
        float gy = 0.f;
        #pragma unroll
        for (int q2 = 1; q2 < 8; q2++) {
            const float a = xs[p + 64 * q1 + 512 * q2];
            gx = fmaf(a, w8q[q2].x, gx);
            gy = fmaf(a, w8q[q2].y, gy);
        }
        const float2 W = T64[(q1 * k1) & 63];
        Hx[q1] = fmaf(gx, W.x, -(gy * W.y));
        Hy[q1] = fmaf(gx, W.y,   gy * W.x);
    }
    #pragma unroll
    for (int q1 = 0; q1 < 8; q1++) {
        sH[q1] = RC * (Hx[q1] + Hy[q1]);
        dH[q1] = RC * (Hy[q1] - Hx[q1]);
    }

    const float2 T64p = T64[p];
    float2 cur, stp;
    {
        const int t0 = p * k1;
        cur = cmulf(T64[t0 >> 6], Tf[t0 & 63]);    // w4096^{p k1}
        const int ts = 8 * p;
        stp = cmulf(T64[ts >> 6], Tf[ts & 63]);    // w4096^{8p}
    }
    __syncthreads();                               // all xs reads complete

    float2* __restrict__ Crow = Cs + p * 65;
    #define S1_STEP(K2) { \
        float bx, by; gather8<K2>(Hx, Hy, sH, dH, bx, by); \
        Crow[k1 + 8 * K2] = make_float2(fmaf(bx, cur.x, -(by * cur.y)), \
                                        fmaf(bx, cur.y,   by * cur.x)); \
        if (k1 + 8 * K2 > 0) {   /* warp-uniform: only k1==0,K2==0 skips */ \
            const float mx = fmaf(T64p.x, cur.x,   T64p.y * cur.y);  \
            const float my = fmaf(T64p.y, cur.x, -(T64p.x * cur.y)); \
            Crow[64 - (k1 + 8 * K2)] = make_float2(                  \
                fmaf(bx, mx,   by * my),                             \
                fmaf(bx, my, -(by * mx)));                           \
        } \
        cur = cmulf(cur, stp); }
    S1_STEP(0) S1_STEP(1) S1_STEP(2) S1_STEP(3)
    #undef S1_STEP
    if (k1 == 0) {                                 // k = 32 (self-mirrored)
        float bx, by; gather8<4>(Hx, Hy, sH, dH, bx, by);
        Crow[32] = make_float2(fmaf(bx, cur.x, -(by * cur.y)),
                               fmaf(bx, cur.y,   by * cur.x));
    }
    __syncthreads();

    // ===== Stage 2: k = tid&63, cls = tid>>6: G2 = cls&1, Qt = cls>>1 =======
    const int k   = tid & 63;
    const int cls = tid >> 6;
    float* __restrict__ outr = out + (size_t)row * ROW_N;

    float acc[16];
    #pragma unroll
    for (int i = 0; i < 16; i++) acc[i] = 0.f;

    switch (cls) {
        case 0: stage2_quarter<0,0>(Cs, T64, k, acc); break;
        case 1: stage2_quarter<1,0>(Cs, T64, k, acc); break;
        case 2: stage2_quarter<0,1>(Cs, T64, k, acc); break;
        case 3: stage2_quarter<1,1>(Cs, T64, k, acc); break;
        case 4: stage2_quarter<0,2>(Cs, T64, k, acc); break;
        case 5: stage2_quarter<1,2>(Cs, T64, k, acc); break;
        case 6: stage2_quarter<0,3>(Cs, T64, k, acc); break;
        default:stage2_quarter<1,3>(Cs, T64, k, acc); break;
    }

    // lone element m = 2048 (needs Cs BEFORE overlay): sum_p (-1)^p Re C[p,0]
    if (tid == 0) {
        float a2 = 0.f;
        #pragma unroll 8
        for (int pp = 0; pp < 64; pp += 2)
            a2 += Cs[pp * 65].x - Cs[(pp + 1) * 65].x;
        outr[2048] = a2;
    }
    __syncthreads();                               // all Cs reads complete

    if (cls >= 2) {                                // quarters 1..3 write partials
        const int u = tid - 128;                   // 0..383
        #pragma unroll
        for (int i = 0; i < 16; i++) Pov[i * 384 + u] = acc[i];
    }
    __syncthreads();

    if (cls < 2) {                                 // quarter 0 combines + stores
        const int G2 = cls;
        #pragma unroll
        for (int q = 1; q < 4; q++) {
            const int u = (2 * q + G2) * 64 + k - 128;
            #pragma unroll
            for (int i = 0; i < 16; i++) acc[i] += Pov[i * 384 + u];
        }
        #pragma unroll
        for (int m = 0; m < 4; m++) {
            #pragma unroll
            for (int j2 = 0; j2 < 4; j2++) {
                const int j  = (G2 + 2 * m) + 8 * j2;    // 0..31
                const int mj = j * 64 + k;               // 0..2047
                const float v = acc[m * 4 + j2];
                outr[mj] = v;                            // coalesced
                if (mj >= 1) outr[ROW_N - mj] = v;       // mirror (incl col 0)
            }
        }
    }
}

extern "C" void kernel_launch(void* const* d_in, const int* in_sizes, int n_in,
                              void* d_out, int out_size)
{
    const float* x = (const float*)d_in[0];
    const int nrows = in_sizes[0] / ROW_N;         // 4096 rows
    if (nrows <= 0) return;
    monarch_fft_kernel<<<nrows, THREADS>>>(x, (float*)d_out);
}

// round 12
// speedup vs baseline: 1.6360x; 1.0649x over previous
#include <cuda_runtime.h>
#include <cuda_bf16.h>

#define ROW_N 4096
#define THREADS 512
#define RC 0.70710678118654752440f

// Monarch FFT, out = Re(FFT(x)) per 4096-pt row; P = Q = 64, radix-8x8 inside
// each 64-pt DFT, Hermitian symmetry everywhere (real input).
// Stage 1 phase A: thread (p,q1) does the real DFT-8 over q2 ONCE (shared by
// all 8 k1 consumers; Hermitian -> only G0/G4,G1,G2,G3 stored), reading x
// directly from global (coalesced). Phase B: thread (p,k1) combines.
// Stage 2: 8 classes = (parity G2) x (quarter Qt), 16 outputs per thread,
// partials exchanged via an overlay on Cs.

__device__ __forceinline__ float2 cmulf(float2 a, float2 b) {
    return make_float2(fmaf(a.x, b.x, -(a.y * b.y)),
                       fmaf(a.x, b.y,   a.y * b.x));
}

template<int M>
__device__ __forceinline__ void rot_add(float hx, float hy, float sh, float dh,
                                        float& bx, float& by)
{
    if constexpr (M == 0)      { bx += hx; by += hy; }
    else if constexpr (M == 1) { bx += sh; by += dh; }
    else if constexpr (M == 2) { bx += hy; by -= hx; }
    else if constexpr (M == 3) { bx += dh; by -= sh; }
    else if constexpr (M == 4) { bx -= hx; by -= hy; }
    else if constexpr (M == 5) { bx -= sh; by -= dh; }
    else if constexpr (M == 6) { bx -= hy; by += hx; }
    else                       { bx -= dh; by += sh; }
}

template<int K2>
__device__ __forceinline__ void gather8(const float (&Hx)[8], const float (&Hy)[8],
                                        const float (&sH)[8], const float (&dH)[8],
                                        float& bx, float& by)
{
    bx = Hx[0]; by = Hy[0];
    rot_add<(1*K2)&7>(Hx[1],Hy[1],sH[1],dH[1],bx,by);
    rot_add<(2*K2)&7>(Hx[2],Hy[2],sH[2],dH[2],bx,by);
    rot_add<(3*K2)&7>(Hx[3],Hy[3],sH[3],dH[3],bx,by);
    rot_add<(4*K2)&7>(Hx[4],Hy[4],sH[4],dH[4],bx,by);
    rot_add<(5*K2)&7>(Hx[5],Hy[5],sH[5],dH[5],bx,by);
    rot_add<(6*K2)&7>(Hx[6],Hy[6],sH[6],dH[6],bx,by);
    rot_add<(7*K2)&7>(Hx[7],Hy[7],sH[7],dH[7],bx,by);
}

// c * e^{-2pi i M/8}
template<int M>
__device__ __forceinline__ float2 crot(float2 c)
{
    if constexpr (M == 0)      return c;
    else if constexpr (M == 1) return make_float2( RC*(c.x+c.y),  RC*(c.y-c.x));
    else if constexpr (M == 2) return make_float2( c.y, -c.x);
    else if constexpr (M == 3) return make_float2( RC*(c.y-c.x), -RC*(c.x+c.y));
    else if constexpr (M == 4) return make_float2(-c.x, -c.y);
    else if constexpr (M == 5) return make_float2(-RC*(c.x+c.y),  RC*(c.x-c.y));
    else if constexpr (M == 6) return make_float2(-c.y,  c.x);
    else                       return make_float2( RC*(c.x-c.y),  RC*(c.x+c.y));
}

// Re( F * e^{-2pi i M/8} )
template<int M>
__device__ __forceinline__ float rot_re(float2 F)
{
    if constexpr (M == 0)      return  F.x;
    else if constexpr (M == 1) return  RC*(F.x+F.y);
    else if constexpr (M == 2) return  F.y;
    else if constexpr (M == 3) return  RC*(F.y-F.x);
    else if constexpr (M == 4) return -F.x;
    else if constexpr (M == 5) return -RC*(F.x+F.y);
    else if constexpr (M == 6) return -F.y;
    else                       return  RC*(F.x-F.y);
}

// Stage-2 one p1: 8 loads -> E_m -> F_m -> Re parts for j2 = 0..3.
template<int P1, int G2>
__device__ __forceinline__ void s2_p1(const float2* __restrict__ Cs,
                                      const float2* __restrict__ T64,
                                      int k, float (&acc)[16])
{
    const float2 u0 = crot<0        >(Cs[(P1 +  0)*65 + k]);
    const float2 u1 = crot<(G2*1)&7>(Cs[(P1 +  8)*65 + k]);
    const float2 u2 = crot<(G2*2)&7>(Cs[(P1 + 16)*65 + k]);
    const float2 u3 = crot<(G2*3)&7>(Cs[(P1 + 24)*65 + k]);
    const float2 u4 = crot<(G2*4)&7>(Cs[(P1 + 32)*65 + k]);
    const float2 u5 = crot<(G2*5)&7>(Cs[(P1 + 40)*65 + k]);
    const float2 u6 = crot<(G2*6)&7>(Cs[(P1 + 48)*65 + k]);
    const float2 u7 = crot<(G2*7)&7>(Cs[(P1 + 56)*65 + k]);

    const float2 s0 = make_float2(u0.x+u4.x, u0.y+u4.y);
    const float2 s1 = make_float2(u1.x+u5.x, u1.y+u5.y);
    const float2 s2 = make_float2(u2.x+u6.x, u2.y+u6.y);
    const float2 s3 = make_float2(u3.x+u7.x, u3.y+u7.y);

    const float2 Pp = make_float2(s0.x+s2.x, s0.y+s2.y);
    const float2 Qq = make_float2(s1.x+s3.x, s1.y+s3.y);
    const float2 Rr = make_float2(s0.x-s2.x, s0.y-s2.y);
    const float2 Ss = make_float2(s1.x-s3.x, s1.y-s3.y);

    const float2 E0 = make_float2(Pp.x+Qq.x, Pp.y+Qq.y);
    const float2 E2 = make_float2(Pp.x-Qq.x, Pp.y-Qq.y);
    const float2 E1 = make_float2(Rr.x+Ss.y, Rr.y-Ss.x);   // R - i S
    const float2 E3 = make_float2(Rr.x-Ss.y, Rr.y+Ss.x);   // R + i S

    {   const float2 F = cmulf(E0, T64[(P1*(G2+0))&63]);
        acc[ 0] += rot_re<0        >(F);
        acc[ 1] += rot_re<(P1*1)&7>(F);
        acc[ 2] += rot_re<(P1*2)&7>(F);
        acc[ 3] += rot_re<(P1*3)&7>(F); }
    {   const float2 F = cmulf(E1, T64[(P1*(G2+2))&63]);
        acc[ 4] += rot_re<0        >(F);
        acc[ 5] += rot_re<(P1*1)&7>(F);
        acc[ 6] += rot_re<(P1*2)&7>(F);
        acc[ 7] += rot_re<(P1*3)&7>(F); }
    {   const float2 F = cmulf(E2, T64[(P1*(G2+4))&63]);
        acc[ 8] += rot_re<0        >(F);
        acc[ 9] += rot_re<(P1*1)&7>(F);
        acc[10] += rot_re<(P1*2)&7>(F);
        acc[11] += rot_re<(P1*3)&7>(F); }
    {   const float2 F = cmulf(E3, T64[(P1*(G2+6))&63]);
        acc[12] += rot_re<0        >(F);
        acc[13] += rot_re<(P1*1)&7>(F);
        acc[14] += rot_re<(P1*2)&7>(F);
        acc[15] += rot_re<(P1*3)&7>(F); }
}

template<int G2, int Qt>
__device__ __forceinline__ void stage2_quarter(const float2* __restrict__ Cs,
                                               const float2* __restrict__ T64,
                                               int k, float (&acc)[16])
{
    s2_p1<Qt,     G2>(Cs, T64, k, acc);
    s2_p1<Qt + 4, G2>(Cs, T64, k, acc);
}

__global__ void __launch_bounds__(THREADS, 2)
monarch_fft_kernel(const float* __restrict__ x, float* __restrict__ out)
{
    __shared__ float2 Cs[64 * 65];   // C[p][k], pitch 65  (33.3 KB)
    __shared__ float2 T64[64];       // e^{-2pi i t/64}
    __shared__ float2 Tf [64];       // e^{-2pi i t/4096}
    float2* Gs  = Cs;                // phase-A G storage (2048 float2 overlay)
    float*  Pov = (float*)Cs;        // stage-2 partial overlay (after reads)

    const int tid = threadIdx.x;
    const int row = blockIdx.x;

    if (tid < 64) {
        float s, c;
        __sincosf(-6.28318530717958647692f * (float)tid * (1.0f / 64.0f), &s, &c);
        T64[tid] = make_float2(c, s);
        __sincosf(-6.28318530717958647692f * (float)tid * (1.0f / 4096.0f), &s, &c);
        Tf[tid] = make_float2(c, s);
    }

    // ===== Phase A: thread (p, q1). Real DFT-8 over q2, direct from gmem ====
    const int p  = tid & 63;
    {
        const int q1a = tid >> 6;
        const float* __restrict__ xr = x + (size_t)row * ROW_N + p + 64 * q1a;
        const float a0 = xr[0],      a1 = xr[512],  a2 = xr[1024], a3 = xr[1536];
        const float a4 = xr[2048],   a5 = xr[2560], a6 = xr[3072], a7 = xr[3584];

        const float s0 = a0 + a4, d0 = a0 - a4;
        const float s1 = a1 + a5, d1 = a1 - a5;
        const float s2 = a2 + a6, d2 = a2 - a6;
        const float s3 = a3 + a7, d3 = a3 - a7;

        const float e02 = s0 + s2, o13 = s1 + s3;
        const float t1 = RC * (d1 - d3);
        const float t2 = RC * (d1 + d3);

        // G0, G4 real (packed); G1..G3 complex; G(8-k) = conj(Gk)
        Gs[(0 * 8 + q1a) * 64 + p] = make_float2(e02 + o13, e02 - o13);
        Gs[(1 * 8 + q1a) * 64 + p] = make_float2(d0 + t1, -(d2 + t2));
        Gs[(2 * 8 + q1a) * 64 + p] = make_float2(s0 - s2, -(s1 - s3));
        Gs[(3 * 8 + q1a) * 64 + p] = make_float2(d0 - t1,   d2 - t2);
    }
    __syncthreads();

    // ===== Phase B: thread (p, k1). H[q1] = G[q1,k1] * w64^{q1 k1} ==========
    const int k1 = tid >> 6;                       // warp-uniform 0..7

    float Hx[8], Hy[8], sH[8], dH[8];
    if (k1 == 0) {
        #pragma unroll
        for (int q1 = 0; q1 < 8; q1++) {
            Hx[q1] = Gs[q1 * 64 + p].x;  Hy[q1] = 0.f;
        }
    } else if (k1 == 4) {
        #pragma unroll
        for (int q1 = 0; q1 < 8; q1++) {
            const float g = Gs[q1 * 64 + p].y;     // G4, times w64^{4 q1}
            const float2 W = T64[(4 * q1) & 63];
            Hx[q1] = g * W.x;  Hy[q1] = g * W.y;
        }
    } else if (k1 < 4) {
        #pragma unroll
        for (int q1 = 0; q1 < 8; q1++) {
            const float2 g = Gs[(k1 * 8 + q1) * 64 + p];
            const float2 W = T64[(q1 * k1) & 63];
            Hx[q1] = fmaf(g.x, W.x, -(g.y * W.y));
            Hy[q1] = fmaf(g.x, W.y,   g.y * W.x);
        }
    } else {
        const int ks = 8 - k1;                     // conj source slot
        #pragma unroll
        for (int q1 = 0; q1 < 8; q1++) {
            const float2 g = Gs[(ks * 8 + q1) * 64 + p];
            const float2 W = T64[(q1 * k1) & 63];
            Hx[q1] = fmaf(g.x, W.x,   g.y * W.y);  // conj: gy -> -gy
            Hy[q1] = fmaf(g.x, W.y, -(g.y * W.x));
        }
    }
    #pragma unroll
    for (int q1 = 0; q1 < 8; q1++) {
        sH[q1] = RC * (Hx[q1] + Hy[q1]);
        dH[q1] = RC * (Hy[q1] - Hx[q1]);
    }

    const float2 T64p = T64[p];
    float2 cur, stp;
    {
        const int t0 = p * k1;
        cur = cmulf(T64[t0 >> 6], Tf[t0 & 63]);    // w4096^{p k1}
        const int ts = 8 * p;
        stp = cmulf(T64[ts >> 6], Tf[ts & 63]);    // w4096^{8p}
    }
    __syncthreads();                               // all G reads complete

    float2* __restrict__ Crow = Cs + p * 65;
    #define S1_STEP(K2) { \
        float bx, by; gather8<K2>(Hx, Hy, sH, dH, bx, by); \
        Crow[k1 + 8 * K2] = make_float2(fmaf(bx, cur.x, -(by * cur.y)), \
                                        fmaf(bx, cur.y,   by * cur.x)); \
        if (k1 + 8 * K2 > 0) {   /* warp-uniform: only k1==0,K2==0 skips */ \
            const float mx = fmaf(T64p.x, cur.x,   T64p.y * cur.y);  \
            const float my = fmaf(T64p.y, cur.x, -(T64p.x * cur.y)); \
            Crow[64 - (k1 + 8 * K2)] = make_float2(                  \
                fmaf(bx, mx,   by * my),                             \
                fmaf(bx, my, -(by * mx)));                           \
        } \
        cur = cmulf(cur, stp); }
    S1_STEP(0) S1_STEP(1) S1_STEP(2) S1_STEP(3)
    #undef S1_STEP
    if (k1 == 0) {                                 // k = 32 (self-mirrored)
        float bx, by; gather8<4>(Hx, Hy, sH, dH, bx, by);
        Crow[32] = make_float2(fmaf(bx, cur.x, -(by * cur.y)),
                               fmaf(bx, cur.y,   by * cur.x));
    }
    __syncthreads();

    // ===== Stage 2: k = tid&63, cls = tid>>6: G2 = cls&1, Qt = cls>>1 =======
    const int k   = tid & 63;
    const int cls = tid >> 6;
    float* __restrict__ outr = out + (size_t)row * ROW_N;

    float acc[16];
    #pragma unroll
    for (int i = 0; i < 16; i++) acc[i] = 0.f;

    switch (cls) {
        case 0: stage2_quarter<0,0>(Cs, T64, k, acc); break;
        case 1: stage2_quarter<1,0>(Cs, T64, k, acc); break;
        case 2: stage2_quarter<0,1>(Cs, T64, k, acc); break;
        case 3: stage2_quarter<1,1>(Cs, T64, k, acc); break;
        case 4: stage2_quarter<0,2>(Cs, T64, k, acc); break;
        case 5: stage2_quarter<1,2>(Cs, T64, k, acc); break;
        case 6: stage2_quarter<0,3>(Cs, T64, k, acc); break;
        default:stage2_quarter<1,3>(Cs, T64, k, acc); break;
    }

    // lone element m = 2048 (needs Cs BEFORE overlay): sum_p (-1)^p Re C[p,0]
    if (tid == 0) {
        float a2 = 0.f;
        #pragma unroll 8
        for (int pp = 0; pp < 64; pp += 2)
            a2 += Cs[pp * 65].x - Cs[(pp + 1) * 65].x;
        outr[2048] = a2;
    }
    __syncthreads();                               // all Cs reads complete

    if (cls >= 2) {                                // quarters 1..3 write partials
        const int u = tid - 128;                   // 0..383
        #pragma unroll
        for (int i = 0; i < 16; i++) Pov[i * 384 + u] = acc[i];
    }
    __syncthreads();

    if (cls < 2) {                                 // quarter 0 combines + stores
        const int G2 = cls;
        #pragma unroll
        for (int q = 1; q < 4; q++) {
            const int u = (2 * q + G2) * 64 + k - 128;
            #pragma unroll
            for (int i = 0; i < 16; i++) acc[i] += Pov[i * 384 + u];
        }
        #pragma unroll
        for (int m = 0; m < 4; m++) {
            #pragma unroll
            for (int j2 = 0; j2 < 4; j2++) {
                const int j  = (G2 + 2 * m) + 8 * j2;    // 0..31
                const int mj = j * 64 + k;               // 0..2047
                const float v = acc[m * 4 + j2];
                outr[mj] = v;                            // coalesced
                if (mj >= 1) outr[ROW_N - mj] = v;       // mirror (incl col 0)
            }
        }
    }
}

extern "C" void kernel_launch(void* const* d_in, const int* in_sizes, int n_in,
                              void* d_out, int out_size)
{
    const float* x = (const float*)d_in[0];
    const int nrows = in_sizes[0] / ROW_N;         // 4096 rows
    if (nrows <= 0) return;
    monarch_fft_kernel<<<nrows, THREADS>>>(x, (float*)d_out);
}

// round 13
// speedup vs baseline: 2.2348x; 1.3660x over previous
#include <cuda_runtime.h>
#include <cuda_bf16.h>

#define ROW_N 4096
#define THREADS 256
#define RC 0.70710678118654752440f

// Monarch FFT, out = Re(FFT(x)) per 4096-pt row; P = Q = 64, radix-8x8 inside
// each 64-pt DFT, Hermitian symmetry everywhere (real input).
// 256 threads/CTA, 4 CTAs/SM (4 independent barrier domains per SM).
// Phase A: thread (p, q1a) does TWO real DFT-8s over q2 (q1 = q1a, q1a+4),
//          reading x directly from global (coalesced).
// Phase B: thread (p, k1a) combines for k1 = k1a and k1a+4; both H-sets are
//          preloaded to registers before the single G->C overlay sync.
// Stage 2: thread (k, cls): G2 = cls&1, p1 in {Qh, Qh+2, Qh+4, Qh+6};
//          partials exchanged via an overlay on Cs.

__device__ __forceinline__ float2 cmulf(float2 a, float2 b) {
    return make_float2(fmaf(a.x, b.x, -(a.y * b.y)),
                       fmaf(a.x, b.y,   a.y * b.x));
}

template<int M>
__device__ __forceinline__ void rot_add(float hx, float hy, float sh, float dh,
                                        float& bx, float& by)
{
    if constexpr (M == 0)      { bx += hx; by += hy; }
    else if constexpr (M == 1) { bx += sh; by += dh; }
    else if constexpr (M == 2) { bx += hy; by -= hx; }
    else if constexpr (M == 3) { bx += dh; by -= sh; }
    else if constexpr (M == 4) { bx -= hx; by -= hy; }
    else if constexpr (M == 5) { bx -= sh; by -= dh; }
    else if constexpr (M == 6) { bx -= hy; by += hx; }
    else                       { bx -= dh; by += sh; }
}

template<int K2>
__device__ __forceinline__ void gather8(const float (&Hx)[8], const float (&Hy)[8],
                                        const float (&sH)[8], const float (&dH)[8],
                                        float& bx, float& by)
{
    bx = Hx[0]; by = Hy[0];
    rot_add<(1*K2)&7>(Hx[1],Hy[1],sH[1],dH[1],bx,by);
    rot_add<(2*K2)&7>(Hx[2],Hy[2],sH[2],dH[2],bx,by);
    rot_add<(3*K2)&7>(Hx[3],Hy[3],sH[3],dH[3],bx,by);
    rot_add<(4*K2)&7>(Hx[4],Hy[4],sH[4],dH[4],bx,by);
    rot_add<(5*K2)&7>(Hx[5],Hy[5],sH[5],dH[5],bx,by);
    rot_add<(6*K2)&7>(Hx[6],Hy[6],sH[6],dH[6],bx,by);
    rot_add<(7*K2)&7>(Hx[7],Hy[7],sH[7],dH[7],bx,by);
}

// c * e^{-2pi i M/8}
template<int M>
__device__ __forceinline__ float2 crot(float2 c)
{
    if constexpr (M == 0)      return c;
    else if constexpr (M == 1) return make_float2( RC*(c.x+c.y),  RC*(c.y-c.x));
    else if constexpr (M == 2) return make_float2( c.y, -c.x);
    else if constexpr (M == 3) return make_float2( RC*(c.y-c.x), -RC*(c.x+c.y));
    else if constexpr (M == 4) return make_float2(-c.x, -c.y);
    else if constexpr (M == 5) return make_float2(-RC*(c.x+c.y),  RC*(c.x-c.y));
    else if constexpr (M == 6) return make_float2(-c.y,  c.x);
    else                       return make_float2( RC*(c.x-c.y),  RC*(c.x+c.y));
}

// Re( F * e^{-2pi i M/8} )
template<int M>
__device__ __forceinline__ float rot_re(float2 F)
{
    if constexpr (M == 0)      return  F.x;
    else if constexpr (M == 1) return  RC*(F.x+F.y);
    else if constexpr (M == 2) return  F.y;
    else if constexpr (M == 3) return  RC*(F.y-F.x);
    else if constexpr (M == 4) return -F.x;
    else if constexpr (M == 5) return -RC*(F.x+F.y);
    else if constexpr (M == 6) return -F.y;
    else                       return  RC*(F.x-F.y);
}

// Stage-2 one p1: 8 loads -> E_m -> F_m -> Re parts for j2 = 0..3.
template<int P1, int G2>
__device__ __forceinline__ void s2_p1(const float2* __restrict__ Cs,
                                      const float2* __restrict__ T64,
                                      int k, float (&acc)[16])
{
    const float2 u0 = crot<0        >(Cs[(P1 +  0)*65 + k]);
    const float2 u1 = crot<(G2*1)&7>(Cs[(P1 +  8)*65 + k]);
    const float2 u2 = crot<(G2*2)&7>(Cs[(P1 + 16)*65 + k]);
    const float2 u3 = crot<(G2*3)&7>(Cs[(P1 + 24)*65 + k]);
    const float2 u4 = crot<(G2*4)&7>(Cs[(P1 + 32)*65 + k]);
    const float2 u5 = crot<(G2*5)&7>(Cs[(P1 + 40)*65 + k]);
    const float2 u6 = crot<(G2*6)&7>(Cs[(P1 + 48)*65 + k]);
    const float2 u7 = crot<(G2*7)&7>(Cs[(P1 + 56)*65 + k]);

    const float2 s0 = make_float2(u0.x+u4.x, u0.y+u4.y);
    const float2 s1 = make_float2(u1.x+u5.x, u1.y+u5.y);
    const float2 s2 = make_float2(u2.x+u6.x, u2.y+u6.y);
    const float2 s3 = make_float2(u3.x+u7.x, u3.y+u7.y);

    const float2 Pp = make_float2(s0.x+s2.x, s0.y+s2.y);
    const float2 Qq = make_float2(s1.x+s3.x, s1.y+s3.y);
    const float2 Rr = make_float2(s0.x-s2.x, s0.y-s2.y);
    const float2 Ss = make_float2(s1.x-s3.x, s1.y-s3.y);

    const float2 E0 = make_float2(Pp.x+Qq.x, Pp.y+Qq.y);
    const float2 E2 = make_float2(Pp.x-Qq.x, Pp.y-Qq.y);
    const float2 E1 = make_float2(Rr.x+Ss.y, Rr.y-Ss.x);   // R - i S
    const float2 E3 = make_float2(Rr.x-Ss.y, Rr.y+Ss.x);   // R + i S

    {   const float2 F = cmulf(E0, T64[(P1*(G2+0))&63]);
        acc[ 0] += rot_re<0        >(F);
        acc[ 1] += rot_re<(P1*1)&7>(F);
        acc[ 2] += rot_re<(P1*2)&7>(F);
        acc[ 3] += rot_re<(P1*3)&7>(F); }
    {   const float2 F = cmulf(E1, T64[(P1*(G2+2))&63]);
        acc[ 4] += rot_re<0        >(F);
        acc[ 5] += rot_re<(P1*1)&7>(F);
        acc[ 6] += rot_re<(P1*2)&7>(F);
        acc[ 7] += rot_re<(P1*3)&7>(F); }
    {   const float2 F = cmulf(E2, T64[(P1*(G2+4))&63]);
        acc[ 8] += rot_re<0        >(F);
        acc[ 9] += rot_re<(P1*1)&7>(F);
        acc[10] += rot_re<(P1*2)&7>(F);
        acc[11] += rot_re<(P1*3)&7>(F); }
    {   const float2 F = cmulf(E3, T64[(P1*(G2+6))&63]);
        acc[12] += rot_re<0        >(F);
        acc[13] += rot_re<(P1*1)&7>(F);
        acc[14] += rot_re<(P1*2)&7>(F);
        acc[15] += rot_re<(P1*3)&7>(F); }
}

template<int G2, int Qh>
__device__ __forceinline__ void stage2_run(const float2* __restrict__ Cs,
                                           const float2* __restrict__ T64,
                                           int k, float (&acc)[16])
{
    s2_p1<Qh,     G2>(Cs, T64, k, acc);
    s2_p1<Qh + 2, G2>(Cs, T64, k, acc);
    s2_p1<Qh + 4, G2>(Cs, T64, k, acc);
    s2_p1<Qh + 6, G2>(Cs, T64, k, acc);
}

__global__ void __launch_bounds__(THREADS, 4)
monarch_fft_kernel(const float* __restrict__ x, float* __restrict__ out)
{
    __shared__ float2 Cs[64 * 65];   // C[p][k], pitch 65  (33.3 KB)
    __shared__ float2 T64[64];       // e^{-2pi i t/64}
    __shared__ float2 Tf [64];       // e^{-2pi i t/4096}
    float2* Gs  = Cs;                // phase-A G storage (2048 float2 overlay)
    float*  Pov = (float*)Cs;        // stage-2 partial overlay (after reads)

    const int tid = threadIdx.x;
    const int row = blockIdx.x;

    if (tid < 64) {
        float s, c;
        __sincosf(-6.28318530717958647692f * (float)tid * (1.0f / 64.0f), &s, &c);
        T64[tid] = make_float2(c, s);
        __sincosf(-6.28318530717958647692f * (float)tid * (1.0f / 4096.0f), &s, &c);
        Tf[tid] = make_float2(c, s);
    }

    // ===== Phase A: thread (p, q1a): real DFT-8 over q2 for q1a, q1a+4 ======
    const int p = tid & 63;
    {
        const int q1a = tid >> 6;                  // 0..3
        #pragma unroll
        for (int pass = 0; pass < 2; pass++) {
            const int q1 = q1a + 4 * pass;
            const float* __restrict__ xr = x + (size_t)row * ROW_N + p + 64 * q1;
            const float a0 = xr[0],    a1 = xr[512],  a2 = xr[1024], a3 = xr[1536];
            const float a4 = xr[2048], a5 = xr[2560], a6 = xr[3072], a7 = xr[3584];

            const float s0 = a0 + a4, d0 = a0 - a4;
            const float s1 = a1 + a5, d1 = a1 - a5;
            const float s2 = a2 + a6, d2 = a2 - a6;
            const float s3 = a3 + a7, d3 = a3 - a7;

            const float e02 = s0 + s2, o13 = s1 + s3;
            const float t1 = RC * (d1 - d3);
            const float t2 = RC * (d1 + d3);

            // G0, G4 real (packed); G1..G3 complex; G(8-k) = conj(Gk)
            Gs[(0 * 8 + q1) * 64 + p] = make_float2(e02 + o13, e02 - o13);
            Gs[(1 * 8 + q1) * 64 + p] = make_float2(d0 + t1, -(d2 + t2));
            Gs[(2 * 8 + q1) * 64 + p] = make_float2(s0 - s2, -(s1 - s3));
            Gs[(3 * 8 + q1) * 64 + p] = make_float2(d0 - t1,   d2 - t2);
        }
    }
    __syncthreads();

    // ===== Phase B: thread (p, k1a): k1 = k1a (0..3) and k1b = k1a+4 ========
    const int k1a = tid >> 6;                      // warp-uniform 0..3
    const int k1b = k1a + 4;                       // 4..7

    float HxA[8], HyA[8], HxB[8], HyB[8];
    if (k1a == 0) {
        #pragma unroll
        for (int q1 = 0; q1 < 8; q1++) {           // k1 = 0: G0 real
            HxA[q1] = Gs[q1 * 64 + p].x;  HyA[q1] = 0.f;
        }
        #pragma unroll
        for (int q1 = 0; q1 < 8; q1++) {           // k1 = 4: G4 real
            const float g = Gs[q1 * 64 + p].y;
            const float2 W = T64[(4 * q1) & 63];
            HxB[q1] = g * W.x;  HyB[q1] = g * W.y;
        }
    } else {
        #pragma unroll
        for (int q1 = 0; q1 < 8; q1++) {           // k1a in 1..3: direct
            const float2 g = Gs[(k1a * 8 + q1) * 64 + p];
            const float2 W = T64[(q1 * k1a) & 63];
            HxA[q1] = fmaf(g.x, W.x, -(g.y * W.y));
            HyA[q1] = fmaf(g.x, W.y,   g.y * W.x);
        }
        const int ks = 8 - k1b;                    // = 4 - k1a, conj source
        #pragma unroll
        for (int q1 = 0; q1 < 8; q1++) {           // k1b in 5..7: conj
            const float2 g = Gs[(ks * 8 + q1) * 64 + p];
            const float2 W = T64[(q1 * k1b) & 63];
            HxB[q1] = fmaf(g.x, W.x,   g.y * W.y);
            HyB[q1] = fmaf(g.x, W.y, -(g.y * W.x));
        }
    }

    const float2 T64p = T64[p];
    float2 curA, curB, stp;
    {
        const int ta = p * k1a;
        curA = cmulf(T64[ta >> 6], Tf[ta & 63]);   // w4096^{p k1a}
        const int tb = p * k1b;
        curB = cmulf(T64[tb >> 6], Tf[tb & 63]);   // w4096^{p k1b}
        const int ts = 8 * p;
        stp = cmulf(T64[ts >> 6], Tf[ts & 63]);    // w4096^{8p}
    }
    __syncthreads();                               // all G reads complete

    float2* __restrict__ Crow = Cs + p * 65;
    {
        float sH[8], dH[8];
        #pragma unroll
        for (int q1 = 0; q1 < 8; q1++) {
            sH[q1] = RC * (HxA[q1] + HyA[q1]);
            dH[q1] = RC * (HyA[q1] - HxA[q1]);
        }
        #define S1_STEP(K2) { \
            float bx, by; gather8<K2>(HxA, HyA, sH, dH, bx, by); \
            Crow[k1a + 8 * K2] = make_float2(fmaf(bx, curA.x, -(by * curA.y)), \
                                             fmaf(bx, curA.y,   by * curA.x)); \
            if (k1a + 8 * K2 > 0) { \
                const float mx = fmaf(T64p.x, curA.x,   T64p.y * curA.y);  \
                const float my = fmaf(T64p.y, curA.x, -(T64p.x * curA.y)); \
                Crow[64 - (k1a + 8 * K2)] = make_float2(                   \
                    fmaf(bx, mx,   by * my),                               \
                    fmaf(bx, my, -(by * mx)));                             \
            } \
            curA = cmulf(curA, stp); }
        S1_STEP(0) S1_STEP(1) S1_STEP(2) S1_STEP(3)
        #undef S1_STEP
        if (k1a == 0) {                            // k = 32 (self-mirrored)
            float bx, by; gather8<4>(HxA, HyA, sH, dH, bx, by);
            Crow[32] = make_float2(fmaf(bx, curA.x, -(by * curA.y)),
                                   fmaf(bx, curA.y,   by * curA.x));
        }
    }
    {
        float sH[8], dH[8];
        #pragma unroll
        for (int q1 = 0; q1 < 8; q1++) {
            sH[q1] = RC * (HxB[q1] + HyB[q1]);
            dH[q1] = RC * (HyB[q1] - HxB[q1]);
        }
        #define S1_STEP(K2) { \
            float bx, by; gather8<K2>(HxB, HyB, sH, dH, bx, by); \
            Crow[k1b + 8 * K2] = make_float2(fmaf(bx, curB.x, -(by * curB.y)), \
                                             fmaf(bx, curB.y,   by * curB.x)); \
            { \
                const float mx = fmaf(T64p.x, curB.x,   T64p.y * curB.y);  \
                const float my = fmaf(T64p.y, curB.x, -(T64p.x * curB.y)); \
                Crow[64 - (k1b + 8 * K2)] = make_float2(                   \
                    fmaf(bx, mx,   by * my),                               \
                    fmaf(bx, my, -(by * mx)));                             \
            } \
            curB = cmulf(curB, stp); }
        S1_STEP(0) S1_STEP(1) S1_STEP(2) S1_STEP(3)
        #undef S1_STEP
    }
    __syncthreads();

    // ===== Stage 2: k = tid&63, cls = tid>>6: G2 = cls&1, Qh = cls>>1 =======
    const int k   = tid & 63;
    const int cls = tid >> 6;                      // 0..3
    float* __restrict__ outr = out + (size_t)row * ROW_N;

    float acc[16];
    #pragma unroll
    for (int i = 0; i < 16; i++) acc[i] = 0.f;

    switch (cls) {
        case 0: stage2_run<0,0>(Cs, T64, k, acc); break;
        case 1: stage2_run<1,0>(Cs, T64, k, acc); break;
        case 2: stage2_run<0,1>(Cs, T64, k, acc); break;
        default:stage2_run<1,1>(Cs, T64, k, acc); break;
    }

    // lone element m = 2048 (needs Cs BEFORE overlay): sum_p (-1)^p Re C[p,0]
    if (tid == 0) {
        float a2 = 0.f;
        #pragma unroll 8
        for (int pp = 0; pp < 64; pp += 2)
            a2 += Cs[pp * 65].x - Cs[(pp + 1) * 65].x;
        outr[2048] = a2;
    }
    __syncthreads();                               // all Cs reads complete

    if (cls >= 2) {                                // Qh = 1 halves write partials
        const int u = tid - 128;                   // 0..127 (= (cls-2)*64 + k)
        #pragma unroll
        for (int i = 0; i < 16; i++) Pov[i * 128 + u] = acc[i];
    }
    __syncthreads();

    if (cls < 2) {                                 // Qh = 0 combines + stores
        const int G2 = cls;
        #pragma unroll
        for (int i = 0; i < 16; i++) acc[i] += Pov[i * 128 + G2 * 64 + k];
        #pragma unroll
        for (int m = 0; m < 4; m++) {
            #pragma unroll
            for (int j2 = 0; j2 < 4; j2++) {
                const int j  = (G2 + 2 * m) + 8 * j2;    // 0..31
                const int mj = j * 64 + k;               // 0..2047
                const float v = acc[m * 4 + j2];
                outr[mj] = v;                            // coalesced
                if (mj >= 1) outr[ROW_N - mj] = v;       // mirror (incl col 0)
            }
        }
    }
}

extern "C" void kernel_launch(void* const* d_in, const int* in_sizes, int n_in,
                              void* d_out, int out_size)
{
    const float* x = (const float*)d_in[0];
    const int nrows = in_sizes[0] / ROW_N;         // 4096 rows
    if (nrows <= 0) return;
    monarch_fft_kernel<<<nrows, THREADS>>>(x, (float*)d_out);
}

// round 14
// speedup vs baseline: 2.3169x; 1.0368x over previous
#include <cuda_runtime.h>
#include <cuda_bf16.h>

#define ROW_N 4096
#define THREADS 256
#define RC 0.70710678118654752440f

// Monarch FFT, out = Re(FFT(x)) per 4096-pt row; P = Q = 64, radix-8x8 inside
// each 64-pt DFT, Hermitian symmetry everywhere (real input).
// 256 threads/CTA, 4 CTAs/SM. C tile uses pitch-64 with XOR-16 column swizzle
// (conflict-free for BOTH p-strided writes and k-consecutive reads).
// f32x2 packed arithmetic (sm_100+) on the element-wise complex adds
// (stage-2 fold) and on phase A's twin q1 passes (lane-split).

// ---- packed f32x2 helpers ----
__device__ __forceinline__ float2 p_add(float2 a, float2 b) {
    unsigned long long r, ua = *(unsigned long long*)&a, ub = *(unsigned long long*)&b;
    asm("add.rn.f32x2 %0, %1, %2;" : "=l"(r) : "l"(ua), "l"(ub));
    return *(float2*)&r;
}
__device__ __forceinline__ float2 p_mul(float2 a, float2 b) {
    unsigned long long r, ua = *(unsigned long long*)&a, ub = *(unsigned long long*)&b;
    asm("mul.rn.f32x2 %0, %1, %2;" : "=l"(r) : "l"(ua), "l"(ub));
    return *(float2*)&r;
}
__device__ __forceinline__ float2 p_fma(float2 a, float2 b, float2 c) {
    unsigned long long r, ua = *(unsigned long long*)&a, ub = *(unsigned long long*)&b,
                       uc = *(unsigned long long*)&c;
    asm("fma.rn.f32x2 %0, %1, %2, %3;" : "=l"(r) : "l"(ua), "l"(ub), "l"(uc));
    return *(float2*)&r;
}
__device__ __forceinline__ float2 p_sub(float2 a, float2 b) {    // a - b, exact
    return p_fma(b, make_float2(-1.f, -1.f), a);
}

__device__ __forceinline__ float2 cmulf(float2 a, float2 b) {
    return make_float2(fmaf(a.x, b.x, -(a.y * b.y)),
                       fmaf(a.x, b.y,   a.y * b.x));
}

template<int M>
__device__ __forceinline__ void rot_add(float hx, float hy, float sh, float dh,
                                        float& bx, float& by)
{
    if constexpr (M == 0)      { bx += hx; by += hy; }
    else if constexpr (M == 1) { bx += sh; by += dh; }
    else if constexpr (M == 2) { bx += hy; by -= hx; }
    else if constexpr (M == 3) { bx += dh; by -= sh; }
    else if constexpr (M == 4) { bx -= hx; by -= hy; }
    else if constexpr (M == 5) { bx -= sh; by -= dh; }
    else if constexpr (M == 6) { bx -= hy; by += hx; }
    else                       { bx -= dh; by += sh; }
}

template<int K2>
__device__ __forceinline__ void gather8(const float (&Hx)[8], const float (&Hy)[8],
                                        const float (&sH)[8], const float (&dH)[8],
                                        float& bx, float& by)
{
    bx = Hx[0]; by = Hy[0];
    rot_add<(1*K2)&7>(Hx[1],Hy[1],sH[1],dH[1],bx,by);
    rot_add<(2*K2)&7>(Hx[2],Hy[2],sH[2],dH[2],bx,by);
    rot_add<(3*K2)&7>(Hx[3],Hy[3],sH[3],dH[3],bx,by);
    rot_add<(4*K2)&7>(Hx[4],Hy[4],sH[4],dH[4],bx,by);
    rot_add<(5*K2)&7>(Hx[5],Hy[5],sH[5],dH[5],bx,by);
    rot_add<(6*K2)&7>(Hx[6],Hy[6],sH[6],dH[6],bx,by);
    rot_add<(7*K2)&7>(Hx[7],Hy[7],sH[7],dH[7],bx,by);
}

// c * e^{-2pi i M/8}
template<int M>
__device__ __forceinline__ float2 crot(float2 c)
{
    if constexpr (M == 0)      return c;
    else if constexpr (M == 1) return make_float2( RC*(c.x+c.y),  RC*(c.y-c.x));
    else if constexpr (M == 2) return make_float2( c.y, -c.x);
    else if constexpr (M == 3) return make_float2( RC*(c.y-c.x), -RC*(c.x+c.y));
    else if constexpr (M == 4) return make_float2(-c.x, -c.y);
    else if constexpr (M == 5) return make_float2(-RC*(c.x+c.y),  RC*(c.x-c.y));
    else if constexpr (M == 6) return make_float2(-c.y,  c.x);
    else                       return make_float2( RC*(c.x-c.y),  RC*(c.x+c.y));
}

// Re( F * e^{-2pi i M/8} )
template<int M>
__device__ __forceinline__ float rot_re(float2 F)
{
    if constexpr (M == 0)      return  F.x;
    else if constexpr (M == 1) return  RC*(F.x+F.y);
    else if constexpr (M == 2) return  F.y;
    else if constexpr (M == 3) return  RC*(F.y-F.x);
    else if constexpr (M == 4) return -F.x;
    else if constexpr (M == 5) return -RC*(F.x+F.y);
    else if constexpr (M == 6) return -F.y;
    else                       return  RC*(F.x-F.y);
}

// Stage-2 one p1: 8 swizzled loads -> packed fold -> F_m -> Re for j2 = 0..3.
template<int P1, int G2>
__device__ __forceinline__ void s2_p1(const float2* __restrict__ Cs,
                                      const float2* __restrict__ T64,
                                      int k, float (&acc)[16])
{
    const int XA = k ^ P1;             // xor consts: (P1+16m)&15 = P1,
    const int XB = k ^ (P1 + 8);       //             (P1+8+16m)&15 = P1+8
    const float2 u0 = crot<0        >(Cs[(P1 +  0)*64 + XA]);
    const float2 u1 = crot<(G2*1)&7>(Cs[(P1 +  8)*64 + XB]);
    const float2 u2 = crot<(G2*2)&7>(Cs[(P1 + 16)*64 + XA]);
    const float2 u3 = crot<(G2*3)&7>(Cs[(P1 + 24)*64 + XB]);
    const float2 u4 = crot<(G2*4)&7>(Cs[(P1 + 32)*64 + XA]);
    const float2 u5 = crot<(G2*5)&7>(Cs[(P1 + 40)*64 + XB]);
    const float2 u6 = crot<(G2*6)&7>(Cs[(P1 + 48)*64 + XA]);
    const float2 u7 = crot<(G2*7)&7>(Cs[(P1 + 56)*64 + XB]);

    const float2 s0 = p_add(u0,u4), s1 = p_add(u1,u5);
    const float2 s2 = p_add(u2,u6), s3 = p_add(u3,u7);
    const float2 Pp = p_add(s0,s2), Qq = p_add(s1,s3);
    const float2 Rr = p_sub(s0,s2), Ss = p_sub(s1,s3);
    const float2 E0 = p_add(Pp,Qq), E2 = p_sub(Pp,Qq);
    const float2 Ssw = make_float2(Ss.y, -Ss.x);
    const float2 E1 = p_add(Rr,Ssw), E3 = p_sub(Rr,Ssw);

    {   const float2 F = cmulf(E0, T64[(P1*(G2+0))&63]);
        acc[ 0] += rot_re<0        >(F);
        acc[ 1] += rot_re<(P1*1)&7>(F);
        acc[ 2] += rot_re<(P1*2)&7>(F);
        acc[ 3] += rot_re<(P1*3)&7>(F); }
    {   const float2 F = cmulf(E1, T64[(P1*(G2+2))&63]);
        acc[ 4] += rot_re<0        >(F);
        acc[ 5] += rot_re<(P1*1)&7>(F);
        acc[ 6] += rot_re<(P1*2)&7>(F);
        acc[ 7] += rot_re<(P1*3)&7>(F); }
    {   const float2 F = cmulf(E2, T64[(P1*(G2+4))&63]);
        acc[ 8] += rot_re<0        >(F);
        acc[ 9] += rot_re<(P1*1)&7>(F);
        acc[10] += rot_re<(P1*2)&7>(F);
        acc[11] += rot_re<(P1*3)&7>(F); }
    {   const float2 F = cmulf(E3, T64[(P1*(G2+6))&63]);
        acc[12] += rot_re<0        >(F);
        acc[13] += rot_re<(P1*1)&7>(F);
        acc[14] += rot_re<(P1*2)&7>(F);
        acc[15] += rot_re<(P1*3)&7>(F); }
}

template<int G2, int Qh>
__device__ __forceinline__ void stage2_run(const float2* __restrict__ Cs,
                                           const float2* __restrict__ T64,
                                           int k, float (&acc)[16])
{
    s2_p1<Qh,     G2>(Cs, T64, k, acc);
    s2_p1<Qh + 2, G2>(Cs, T64, k, acc);
    s2_p1<Qh + 4, G2>(Cs, T64, k, acc);
    s2_p1<Qh + 6, G2>(Cs, T64, k, acc);
}

__global__ void __launch_bounds__(THREADS, 4)
monarch_fft_kernel(const float* __restrict__ x, float* __restrict__ out)
{
    __shared__ float2 Cs[64 * 64];   // C[p][k^(p&15)], XOR-swizzled (32 KB)
    __shared__ float2 T64[64];       // e^{-2pi i t/64}
    __shared__ float2 Tf [64];       // e^{-2pi i t/4096}
    float2* Gs  = Cs;                // phase-A G storage (2048 float2 overlay)
    float*  Pov = (float*)Cs;        // stage-2 partial overlay (after reads)

    const int tid = threadIdx.x;
    const int row = blockIdx.x;

    if (tid < 64) {
        float s, c;
        __sincosf(-6.28318530717958647692f * (float)tid * (1.0f / 64.0f), &s, &c);
        T64[tid] = make_float2(c, s);
        __sincosf(-6.28318530717958647692f * (float)tid * (1.0f / 4096.0f), &s, &c);
        Tf[tid] = make_float2(c, s);
    }

    // ===== Phase A: thread (p, q1a): packed twin real DFT-8 over q2 =========
    // f32x2 lanes = (q1 = q1a, q1 = q1a+4).
    const int p = tid & 63;
    {
        const int q1a = tid >> 6;                  // 0..3
        const float2 RC2 = make_float2(RC, RC);
        const float* __restrict__ xr = x + (size_t)row * ROW_N + p + 64 * q1a;
        const float2 a0 = make_float2(xr[   0], xr[ 256]);
        const float2 a1 = make_float2(xr[ 512], xr[ 768]);
        const float2 a2 = make_float2(xr[1024], xr[1280]);
        const float2 a3 = make_float2(xr[1536], xr[1792]);
        const float2 a4 = make_float2(xr[2048], xr[2304]);
        const float2 a5 = make_float2(xr[2560], xr[2816]);
        const float2 a6 = make_float2(xr[3072], xr[3328]);
        const float2 a7 = make_float2(xr[3584], xr[3840]);

        const float2 s0 = p_add(a0,a4), d0 = p_sub(a0,a4);
        const float2 s1 = p_add(a1,a5), d1 = p_sub(a1,a5);
        const float2 s2 = p_add(a2,a6), d2 = p_sub(a2,a6);
        const float2 s3 = p_add(a3,a7), d3 = p_sub(a3,a7);

        const float2 e02 = p_add(s0,s2), o13 = p_add(s1,s3);
        const float2 t1 = p_mul(p_sub(d1,d3), RC2);
        const float2 t2 = p_mul(p_add(d1,d3), RC2);

        const float2 g0a = p_add(e02,o13), g0b = p_sub(e02,o13);
        const float2 g1r = p_add(d0,t1);
        const float2 g1i = p_mul(p_add(d2,t2), make_float2(-1.f,-1.f));
        const float2 g2r = p_sub(s0,s2),  g2i = p_sub(s3,s1);   // -(s1-s3)
        const float2 g3r = p_sub(d0,t1),  g3i = p_sub(d2,t2);

        // G0/G4 packed real; G1..G3 complex; G(8-k) = conj(Gk)
        Gs[(0 * 8 + q1a    ) * 64 + p] = make_float2(g0a.x, g0b.x);
        Gs[(1 * 8 + q1a    ) * 64 + p] = make_float2(g1r.x, g1i.x);
        Gs[(2 * 8 + q1a    ) * 64 + p] = make_float2(g2r.x, g2i.x);
        Gs[(3 * 8 + q1a    ) * 64 + p] = make_float2(g3r.x, g3i.x);
        Gs[(0 * 8 + q1a + 4) * 64 + p] = make_float2(g0a.y, g0b.y);
        Gs[(1 * 8 + q1a + 4) * 64 + p] = make_float2(g1r.y, g1i.y);
        Gs[(2 * 8 + q1a + 4) * 64 + p] = make_float2(g2r.y, g2i.y);
        Gs[(3 * 8 + q1a + 4) * 64 + p] = make_float2(g3r.y, g3i.y);
    }
    __syncthreads();

    // ===== Phase B: thread (p, k1a): k1 = k1a (0..3) and k1b = k1a+4 ========
    const int k1a = tid >> 6;                      // warp-uniform 0..3
    const int k1b = k1a + 4;                       // 4..7

    float HxA[8], HyA[8], HxB[8], HyB[8];
    if (k1a == 0) {
        #pragma unroll
        for (int q1 = 0; q1 < 8; q1++) {           // k1 = 0: G0 real
            HxA[q1] = Gs[q1 * 64 + p].x;  HyA[q1] = 0.f;
        }
        #pragma unroll
        for (int q1 = 0; q1 < 8; q1++) {           // k1 = 4: G4 real
            const float g = Gs[q1 * 64 + p].y;
            const float2 W = T64[(4 * q1) & 63];
            HxB[q1] = g * W.x;  HyB[q1] = g * W.y;
        }
    } else {
        #pragma unroll
        for (int q1 = 0; q1 < 8; q1++) {           // k1a in 1..3: direct
            const float2 g = Gs[(k1a * 8 + q1) * 64 + p];
            const float2 W = T64[(q1 * k1a) & 63];
            HxA[q1] = fmaf(g.x, W.x, -(g.y * W.y));
            HyA[q1] = fmaf(g.x, W.y,   g.y * W.x);
        }
        const int ks = 8 - k1b;                    // conj source slot
        #pragma unroll
        for (int q1 = 0; q1 < 8; q1++) {           // k1b in 5..7: conj
            const float2 g = Gs[(ks * 8 + q1) * 64 + p];
            const float2 W = T64[(q1 * k1b) & 63];
            HxB[q1] = fmaf(g.x, W.x,   g.y * W.y);
            HyB[q1] = fmaf(g.x, W.y, -(g.y * W.x));
        }
    }

    const float2 T64p = T64[p];
    float2 curA, curB, stp;
    {
        const int ta = p * k1a;
        curA = cmulf(T64[ta >> 6], Tf[ta & 63]);   // w4096^{p k1a}
        const int tb = p * k1b;
        curB = cmulf(T64[tb >> 6], Tf[tb & 63]);   // w4096^{p k1b}
        const int ts = 8 * p;
        stp = cmulf(T64[ts >> 6], Tf[ts & 63]);    // w4096^{8p}
    }
    __syncthreads();                               // all G reads complete

    const int pxor = p & 15;
    float2* __restrict__ Crow = Cs + p * 64;
    #define CSW(c) Crow[(c) ^ pxor]
    {
        float sH[8], dH[8];
        #pragma unroll
        for (int q1 = 0; q1 < 8; q1++) {
            sH[q1] = RC * (HxA[q1] + HyA[q1]);
            dH[q1] = RC * (HyA[q1] - HxA[q1]);
        }
        #define S1_STEP(K2) { \
            float bx, by; gather8<K2>(HxA, HyA, sH, dH, bx, by); \
            CSW(k1a + 8 * K2) = make_float2(fmaf(bx, curA.x, -(by * curA.y)), \
                                            fmaf(bx, curA.y,   by * curA.x)); \
            if (k1a + 8 * K2 > 0) { \
                const float mx = fmaf(T64p.x, curA.x,   T64p.y * curA.y);  \
                const float my = fmaf(T64p.y, curA.x, -(T64p.x * curA.y)); \
                CSW(64 - (k1a + 8 * K2)) = make_float2(                    \
                    fmaf(bx, mx,   by * my),                               \
                    fmaf(bx, my, -(by * mx)));                             \
            } \
            curA = cmulf(curA, stp); }
        S1_STEP(0) S1_STEP(1) S1_STEP(2) S1_STEP(3)
        #undef S1_STEP
        if (k1a == 0) {                            // k = 32 (self-mirrored)
            float bx, by; gather8<4>(HxA, HyA, sH, dH, bx, by);
            CSW(32) = make_float2(fmaf(bx, curA.x, -(by * curA.y)),
                                  fmaf(bx, curA.y,   by * curA.x));
        }
    }
    {
        float sH[8], dH[8];
        #pragma unroll
        for (int q1 = 0; q1 < 8; q1++) {
            sH[q1] = RC * (HxB[q1] + HyB[q1]);
            dH[q1] = RC * (HyB[q1] - HxB[q1]);
        }
        #define S1_STEP(K2) { \
            float bx, by; gather8<K2>(HxB, HyB, sH, dH, bx, by); \
            CSW(k1b + 8 * K2) = make_float2(fmaf(bx, curB.x, -(by * curB.y)), \
                                            fmaf(bx, curB.y,   by * curB.x)); \
            { \
                const float mx = fmaf(T64p.x, curB.x,   T64p.y * curB.y);  \
                const float my = fmaf(T64p.y, curB.x, -(T64p.x * curB.y)); \
                CSW(64 - (k1b + 8 * K2)) = make_float2(                    \
                    fmaf(bx, mx,   by * my),                               \
                    fmaf(bx, my, -(by * mx)));                             \
            } \
            curB = cmulf(curB, stp); }
        S1_STEP(0) S1_STEP(1) S1_STEP(2) S1_STEP(3)
        #undef S1_STEP
    }
    #undef CSW
    __syncthreads();

    // ===== Stage 2: k = tid&63, cls = tid>>6: G2 = cls&1, Qh = cls>>1 =======
    const int k   = tid & 63;
    const int cls = tid >> 6;                      // 0..3
    float* __restrict__ outr = out + (size_t)row * ROW_N;

    float acc[16];
    #pragma unroll
    for (int i = 0; i < 16; i++) acc[i] = 0.f;

    switch (cls) {
        case 0: stage2_run<0,0>(Cs, T64, k, acc); break;
        case 1: stage2_run<1,0>(Cs, T64, k, acc); break;
        case 2: stage2_run<0,1>(Cs, T64, k, acc); break;
        default:stage2_run<1,1>(Cs, T64, k, acc); break;
    }

    // lone element m = 2048 (needs Cs BEFORE overlay): sum_p (-1)^p Re C[p,0]
    if (tid == 0) {
        float a2 = 0.f;
        #pragma unroll 8
        for (int pp = 0; pp < 64; pp += 2)
            a2 += Cs[pp * 64 + (pp & 15)].x
                - Cs[(pp + 1) * 64 + ((pp + 1) & 15)].x;
        outr[2048] = a2;
    }
    __syncthreads();                               // all Cs reads complete

    if (cls >= 2) {                                // Qh = 1 halves write partials
        const int u = tid - 128;                   // 0..127 (= (cls-2)*64 + k)
        #pragma unroll
        for (int i = 0; i < 16; i++) Pov[i * 128 + u] = acc[i];
    }
    __syncthreads();

    if (cls < 2) {                                 // Qh = 0 combines + stores
        const int G2 = cls;
        #pragma unroll
        for (int i = 0; i < 16; i++) acc[i] += Pov[i * 128 + G2 * 64 + k];
        #pragma unroll
        for (int m = 0; m < 4; m++) {
            #pragma unroll
            for (int j2 = 0; j2 < 4; j2++) {
                const int j  = (G2 + 2 * m) + 8 * j2;    // 0..31
                const int mj = j * 64 + k;               // 0..2047
                const float v = acc[m * 4 + j2];
                outr[mj] = v;                            // coalesced
                if (mj >= 1) outr[ROW_N - mj] = v;       // mirror (incl col 0)
            }
        }
    }
}

extern "C" void kernel_launch(void* const* d_in, const int* in_sizes, int n_in,
                              void* d_out, int out_size)
{
    const float* x = (const float*)d_in[0];
    const int nrows = in_sizes[0] / ROW_N;         // 4096 rows
    if (nrows <= 0) return;
    monarch_fft_kernel<<<nrows, THREADS>>>(x, (float*)d_out);
}

// round 15
// speedup vs baseline: 2.3186x; 1.0007x over previous
#include <cuda_runtime.h>
#include <cuda_bf16.h>

#define ROW_N 4096
#define THREADS 256
#define RC 0.70710678118654752440f

// Monarch FFT, out = Re(FFT(x)) per 4096-pt row; P = Q = 64, radix-8x8 inside
// each 64-pt DFT, Hermitian symmetry everywhere (real input).
// 256 threads/CTA, 4 CTAs/SM. C tile: pitch-64, XOR-16 column swizzle
// (conflict-free for p-strided 64-bit writes AND k-consecutive reads).
// Phase A: scalar twin real DFT-8 (no pack/unpack overhead).
// Phase B: gather with INLINE sqrt2-rotations (no sH/dH arrays -> no spills).
// Stage 2: packed f32x2 fold on naturally-paired LDS.64 data.

// ---- packed f32x2 helpers (used only on register-pair-aligned data) ----
__device__ __forceinline__ float2 p_add(float2 a, float2 b) {
    unsigned long long r, ua = *(unsigned long long*)&a, ub = *(unsigned long long*)&b;
    asm("add.rn.f32x2 %0, %1, %2;" : "=l"(r) : "l"(ua), "l"(ub));
    return *(float2*)&r;
}
__device__ __forceinline__ float2 p_fma(float2 a, float2 b, float2 c) {
    unsigned long long r, ua = *(unsigned long long*)&a, ub = *(unsigned long long*)&b,
                       uc = *(unsigned long long*)&c;
    asm("fma.rn.f32x2 %0, %1, %2, %3;" : "=l"(r) : "l"(ua), "l"(ub), "l"(uc));
    return *(float2*)&r;
}
__device__ __forceinline__ float2 p_sub(float2 a, float2 b) {    // a - b, exact
    return p_fma(b, make_float2(-1.f, -1.f), a);
}

__device__ __forceinline__ float2 cmulf(float2 a, float2 b) {
    return make_float2(fmaf(a.x, b.x, -(a.y * b.y)),
                       fmaf(a.x, b.y,   a.y * b.x));
}

// (bx,by) += h * e^{-2pi i M/8}; sqrt2 terms computed inline (no cached arrays)
template<int M>
__device__ __forceinline__ void rot_add(float hx, float hy, float& bx, float& by)
{
    if constexpr (M == 0)      { bx += hx; by += hy; }
    else if constexpr (M == 1) { bx = fmaf(RC, hx + hy, bx); by = fmaf(RC, hy - hx, by); }
    else if constexpr (M == 2) { bx += hy; by -= hx; }
    else if constexpr (M == 3) { bx = fmaf(RC, hy - hx, bx); by = fmaf(-RC, hx + hy, by); }
    else if constexpr (M == 4) { bx -= hx; by -= hy; }
    else if constexpr (M == 5) { bx = fmaf(-RC, hx + hy, bx); by = fmaf(RC, hx - hy, by); }
    else if constexpr (M == 6) { bx -= hy; by += hx; }
    else                       { bx = fmaf(RC, hx - hy, bx); by = fmaf(RC, hx + hy, by); }
}

template<int K2>
__device__ __forceinline__ void gather8(const float (&Hx)[8], const float (&Hy)[8],
                                        float& bx, float& by)
{
    bx = Hx[0]; by = Hy[0];
    rot_add<(1*K2)&7>(Hx[1],Hy[1],bx,by);
    rot_add<(2*K2)&7>(Hx[2],Hy[2],bx,by);
    rot_add<(3*K2)&7>(Hx[3],Hy[3],bx,by);
    rot_add<(4*K2)&7>(Hx[4],Hy[4],bx,by);
    rot_add<(5*K2)&7>(Hx[5],Hy[5],bx,by);
    rot_add<(6*K2)&7>(Hx[6],Hy[6],bx,by);
    rot_add<(7*K2)&7>(Hx[7],Hy[7],bx,by);
}

// c * e^{-2pi i M/8}
template<int M>
__device__ __forceinline__ float2 crot(float2 c)
{
    if constexpr (M == 0)      return c;
    else if constexpr (M == 1) return make_float2( RC*(c.x+c.y),  RC*(c.y-c.x));
    else if constexpr (M == 2) return make_float2( c.y, -c.x);
    else if constexpr (M == 3) return make_float2( RC*(c.y-c.x), -RC*(c.x+c.y));
    else if constexpr (M == 4) return make_float2(-c.x, -c.y);
    else if constexpr (M == 5) return make_float2(-RC*(c.x+c.y),  RC*(c.x-c.y));
    else if constexpr (M == 6) return make_float2(-c.y,  c.x);
    else                       return make_float2( RC*(c.x-c.y),  RC*(c.x+c.y));
}

// Re( F * e^{-2pi i M/8} )
template<int M>
__device__ __forceinline__ float rot_re(float2 F)
{
    if constexpr (M == 0)      return  F.x;
    else if constexpr (M == 1) return  RC*(F.x+F.y);
    else if constexpr (M == 2) return  F.y;
    else if constexpr (M == 3) return  RC*(F.y-F.x);
    else if constexpr (M == 4) return -F.x;
    else if constexpr (M == 5) return -RC*(F.x+F.y);
    else if constexpr (M == 6) return -F.y;
    else                       return  RC*(F.x-F.y);
}

// Stage-2 one p1: 8 swizzled loads -> packed fold -> F_m -> Re for j2 = 0..3.
template<int P1, int G2>
__device__ __forceinline__ void s2_p1(const float2* __restrict__ Cs,
                                      const float2* __restrict__ T64,
                                      int k, float (&acc)[16])
{
    const int XA = k ^ P1;             // xor consts: (P1+16m)&15 = P1,
    const int XB = k ^ (P1 + 8);       //             (P1+8+16m)&15 = P1+8
    const float2 u0 = crot<0        >(Cs[(P1 +  0)*64 + XA]);
    const float2 u1 = crot<(G2*1)&7>(Cs[(P1 +  8)*64 + XB]);
    const float2 u2 = crot<(G2*2)&7>(Cs[(P1 + 16)*64 + XA]);
    const float2 u3 = crot<(G2*3)&7>(Cs[(P1 + 24)*64 + XB]);
    const float2 u4 = crot<(G2*4)&7>(Cs[(P1 + 32)*64 + XA]);
    const float2 u5 = crot<(G2*5)&7>(Cs[(P1 + 40)*64 + XB]);
    const float2 u6 = crot<(G2*6)&7>(Cs[(P1 + 48)*64 + XA]);
    const float2 u7 = crot<(G2*7)&7>(Cs[(P1 + 56)*64 + XB]);

    const float2 s0 = p_add(u0,u4), s1 = p_add(u1,u5);
    const float2 s2 = p_add(u2,u6), s3 = p_add(u3,u7);
    const float2 Pp = p_add(s0,s2), Qq = p_add(s1,s3);
    const float2 Rr = p_sub(s0,s2), Ss = p_sub(s1,s3);
    const float2 E0 = p_add(Pp,Qq), E2 = p_sub(Pp,Qq);
    const float2 Ssw = make_float2(Ss.y, -Ss.x);
    const float2 E1 = p_add(Rr,Ssw), E3 = p_sub(Rr,Ssw);

    {   const float2 F = cmulf(E0, T64[(P1*(G2+0))&63]);
        acc[ 0] += rot_re<0        >(F);
        acc[ 1] += rot_re<(P1*1)&7>(F);
        acc[ 2] += rot_re<(P1*2)&7>(F);
        acc[ 3] += rot_re<(P1*3)&7>(F); }
    {   const float2 F = cmulf(E1, T64[(P1*(G2+2))&63]);
        acc[ 4] += rot_re<0        >(F);
        acc[ 5] += rot_re<(P1*1)&7>(F);
        acc[ 6] += rot_re<(P1*2)&7>(F);
        acc[ 7] += rot_re<(P1*3)&7>(F); }
    {   const float2 F = cmulf(E2, T64[(P1*(G2+4))&63]);
        acc[ 8] += rot_re<0        >(F);
        acc[ 9] += rot_re<(P1*1)&7>(F);
        acc[10] += rot_re<(P1*2)&7>(F);
        acc[11] += rot_re<(P1*3)&7>(F); }
    {   const float2 F = cmulf(E3, T64[(P1*(G2+6))&63]);
        acc[12] += rot_re<0        >(F);
        acc[13] += rot_re<(P1*1)&7>(F);
        acc[14] += rot_re<(P1*2)&7>(F);
        acc[15] += rot_re<(P1*3)&7>(F); }
}

template<int G2, int Qh>
__device__ __forceinline__ void stage2_run(const float2* __restrict__ Cs,
                                           const float2* __restrict__ T64,
                                           int k, float (&acc)[16])
{
    s2_p1<Qh,     G2>(Cs, T64, k, acc);
    s2_p1<Qh + 2, G2>(Cs, T64, k, acc);
    s2_p1<Qh + 4, G2>(Cs, T64, k, acc);
    s2_p1<Qh + 6, G2>(Cs, T64, k, acc);
}

__global__ void __launch_bounds__(THREADS, 4)
monarch_fft_kernel(const float* __restrict__ x, float* __restrict__ out)
{
    __shared__ float2 Cs[64 * 64];   // C[p][k^(p&15)], XOR-swizzled (32 KB)
    __shared__ float2 T64[64];       // e^{-2pi i t/64}
    __shared__ float2 Tf [64];       // e^{-2pi i t/4096}
    float2* Gs  = Cs;                // phase-A G storage (2048 float2 overlay)
    float*  Pov = (float*)Cs;        // stage-2 partial overlay (after reads)

    const int tid = threadIdx.x;
    const int row = blockIdx.x;

    if (tid < 64) {
        float s, c;
        __sincosf(-6.28318530717958647692f * (float)tid * (1.0f / 64.0f), &s, &c);
        T64[tid] = make_float2(c, s);
        __sincosf(-6.28318530717958647692f * (float)tid * (1.0f / 4096.0f), &s, &c);
        Tf[tid] = make_float2(c, s);
    }

    // ===== Phase A: thread (p, q1a): scalar real DFT-8 over q2, twice =======
    const int p = tid & 63;
    {
        const int q1a = tid >> 6;                  // 0..3
        #pragma unroll
        for (int pass = 0; pass < 2; pass++) {
            const int q1 = q1a + 4 * pass;
            const float* __restrict__ xr = x + (size_t)row * ROW_N + p + 64 * q1;
            const float a0 = xr[0],    a1 = xr[512],  a2 = xr[1024], a3 = xr[1536];
            const float a4 = xr[2048], a5 = xr[2560], a6 = xr[3072], a7 = xr[3584];

            const float s0 = a0 + a4, d0 = a0 - a4;
            const float s1 = a1 + a5, d1 = a1 - a5;
            const float s2 = a2 + a6, d2 = a2 - a6;
            const float s3 = a3 + a7, d3 = a3 - a7;

            const float e02 = s0 + s2, o13 = s1 + s3;
            const float t1 = RC * (d1 - d3);
            const float t2 = RC * (d1 + d3);

            // G0, G4 real (packed); G1..G3 complex; G(8-k) = conj(Gk)
            Gs[(0 * 8 + q1) * 64 + p] = make_float2(e02 + o13, e02 - o13);
            Gs[(1 * 8 + q1) * 64 + p] = make_float2(d0 + t1, -(d2 + t2));
            Gs[(2 * 8 + q1) * 64 + p] = make_float2(s0 - s2, -(s1 - s3));
            Gs[(3 * 8 + q1) * 64 + p] = make_float2(d0 - t1,   d2 - t2);
        }
    }
    __syncthreads();

    // ===== Phase B: thread (p, k1a): k1 = k1a (0..3) and k1b = k1a+4 ========
    const int k1a = tid >> 6;                      // warp-uniform 0..3
    const int k1b = k1a + 4;                       // 4..7

    float HxA[8], HyA[8], HxB[8], HyB[8];
    if (k1a == 0) {
        #pragma unroll
        for (int q1 = 0; q1 < 8; q1++) {           // k1 = 0: G0 real
            HxA[q1] = Gs[q1 * 64 + p].x;  HyA[q1] = 0.f;
        }
        #pragma unroll
        for (int q1 = 0; q1 < 8; q1++) {           // k1 = 4: G4 real
            const float g = Gs[q1 * 64 + p].y;
            const float2 W = T64[(4 * q1) & 63];
            HxB[q1] = g * W.x;  HyB[q1] = g * W.y;
        }
    } else {
        #pragma unroll
        for (int q1 = 0; q1 < 8; q1++) {           // k1a in 1..3: direct
            const float2 g = Gs[(k1a * 8 + q1) * 64 + p];
            const float2 W = T64[(q1 * k1a) & 63];
            HxA[q1] = fmaf(g.x, W.x, -(g.y * W.y));
            HyA[q1] = fmaf(g.x, W.y,   g.y * W.x);
        }
        const int ks = 8 - k1b;                    // conj source slot
        #pragma unroll
        for (int q1 = 0; q1 < 8; q1++) {           // k1b in 5..7: conj
            const float2 g = Gs[(ks * 8 + q1) * 64 + p];
            const float2 W = T64[(q1 * k1b) & 63];
            HxB[q1] = fmaf(g.x, W.x,   g.y * W.y);
            HyB[q1] = fmaf(g.x, W.y, -(g.y * W.x));
        }
    }

    const float2 T64p = T64[p];
    float2 curA, curB, stp;
    {
        const int ta = p * k1a;
        curA = cmulf(T64[ta >> 6], Tf[ta & 63]);   // w4096^{p k1a}
        const int tb = p * k1b;
        curB = cmulf(T64[tb >> 6], Tf[tb & 63]);   // w4096^{p k1b}
        const int ts = 8 * p;
        stp = cmulf(T64[ts >> 6], Tf[ts & 63]);    // w4096^{8p}
    }
    __syncthreads();                               // all G reads complete

    const int pxor = p & 15;
    float2* __restrict__ Crow = Cs + p * 64;
    #define CSW(c) Crow[(c) ^ pxor]
    {
        #define S1_STEP(K2) { \
            float bx, by; gather8<K2>(HxA, HyA, bx, by); \
            CSW(k1a + 8 * K2) = make_float2(fmaf(bx, curA.x, -(by * curA.y)), \
                                            fmaf(bx, curA.y,   by * curA.x)); \
            if (k1a + 8 * K2 > 0) { \
                const float mx = fmaf(T64p.x, curA.x,   T64p.y * curA.y);  \
                const float my = fmaf(T64p.y, curA.x, -(T64p.x * curA.y)); \
                CSW(64 - (k1a + 8 * K2)) = make_float2(                    \
                    fmaf(bx, mx,   by * my),                               \
                    fmaf(bx, my, -(by * mx)));                             \
            } \
            curA = cmulf(curA, stp); }
        S1_STEP(0) S1_STEP(1) S1_STEP(2) S1_STEP(3)
        #undef S1_STEP
        if (k1a == 0) {                            // k = 32 (self-mirrored)
            float bx, by; gather8<4>(HxA, HyA, bx, by);
            CSW(32) = make_float2(fmaf(bx, curA.x, -(by * curA.y)),
                                  fmaf(bx, curA.y,   by * curA.x));
        }
    }
    {
        #define S1_STEP(K2) { \
            float bx, by; gather8<K2>(HxB, HyB, bx, by); \
            CSW(k1b + 8 * K2) = make_float2(fmaf(bx, curB.x, -(by * curB.y)), \
                                            fmaf(bx, curB.y,   by * curB.x)); \
            { \
                const float mx = fmaf(T64p.x, curB.x,   T64p.y * curB.y);  \
                const float my = fmaf(T64p.y, curB.x, -(T64p.x * curB.y)); \
                CSW(64 - (k1b + 8 * K2)) = make_float2(                    \
                    fmaf(bx, mx,   by * my),                               \
                    fmaf(bx, my, -(by * mx)));                             \
            } \
            curB = cmulf(curB, stp); }
        S1_STEP(0) S1_STEP(1) S1_STEP(2) S1_STEP(3)
        #undef S1_STEP
    }
    #undef CSW
    __syncthreads();

    // ===== Stage 2: k = tid&63, cls = tid>>6: G2 = cls&1, Qh = cls>>1 =======
    const int k   = tid & 63;
    const int cls = tid >> 6;                      // 0..3
    float* __restrict__ outr = out + (size_t)row * ROW_N;

    float acc[16];
    #pragma unroll
    for (int i = 0; i < 16; i++) acc[i] = 0.f;

    switch (cls) {
        case 0: stage2_run<0,0>(Cs, T64, k, acc); break;
        case 1: stage2_run<1,0>(Cs, T64, k, acc); break;
        case 2: stage2_run<0,1>(Cs, T64, k, acc); break;
        default:stage2_run<1,1>(Cs, T64, k, acc); break;
    }

    // lone element m = 2048 (needs Cs BEFORE overlay): sum_p (-1)^p Re C[p,0]
    if (tid == 0) {
        float a2 = 0.f;
        #pragma unroll 8
        for (int pp = 0; pp < 64; pp += 2)
            a2 += Cs[pp * 64 + (pp & 15)].x
                - Cs[(pp + 1) * 64 + ((pp + 1) & 15)].x;
        outr[2048] = a2;
    }
    __syncthreads();                               // all Cs reads complete

    if (cls >= 2) {                                // Qh = 1 halves write partials
        const int u = tid - 128;                   // 0..127 (= (cls-2)*64 + k)
        #pragma unroll
        for (int i = 0; i < 16; i++) Pov[i * 128 + u] = acc[i];
    }
    __syncthreads();

    if (cls < 2) {                                 // Qh = 0 combines + stores
        const int G2 = cls;
        #pragma unroll
        for (int i = 0; i < 16; i++) acc[i] += Pov[i * 128 + G2 * 64 + k];
        #pragma unroll
        for (int m = 0; m < 4; m++) {
            #pragma unroll
            for (int j2 = 0; j2 < 4; j2++) {
                const int j  = (G2 + 2 * m) + 8 * j2;    // 0..31
                const int mj = j * 64 + k;               // 0..2047
                const float v = acc[m * 4 + j2];
                outr[mj] = v;                            // coalesced
                if (mj >= 1) outr[ROW_N - mj] = v;       // mirror (incl col 0)
            }
        }
    }
}

extern "C" void kernel_launch(void* const* d_in, const int* in_sizes, int n_in,
                              void* d_out, int out_size)
{
    const float* x = (const float*)d_in[0];
    const int nrows = in_sizes[0] / ROW_N;         // 4096 rows
    if (nrows <= 0) return;
    monarch_fft_kernel<<<nrows, THREADS>>>(x, (float*)d_out);
}